// round 11
// baseline (speedup 1.0000x reference)
#include <cuda_runtime.h>
#include <cuda_bf16.h>
#include <cstdint>

#define NB_B 1024
#define FAN_1 15
#define FAN_2 10
#define EMB 256
#define HID 512
#define HEADS 8
#define N1 (NB_B * FAN_1)
#define N2 (N1 * FAN_2)
#define W4 (HID * EMB / 4)

typedef __nv_bfloat16 bf;

// ---------------- scratch (16B-aligned for cp.async) ----------------
__device__ int g_seeds[NB_B];
__device__ int g_nbr1[N1];
__device__ int g_nbr2[N2];
__device__ __align__(16) bf g_Bs1hi[HID * EMB], g_Bs1lo[HID * EMB];
__device__ __align__(16) bf g_Bq1hi[HID * EMB], g_Bq1lo[HID * EMB];
__device__ __align__(16) bf g_B2chi[2 * HID * EMB], g_B2clo[2 * HID * EMB];  // [Ws2;Wq2]
__device__ __align__(16) bf g_Wv1hi[HID * EMB], g_Wv1lo[HID * EMB];
__device__ __align__(16) bf g_Wv2hi[HID * HID], g_Wv2lo[HID * HID];
__device__ __align__(16) bf g_Wk1thi[HEADS * EMB * 64], g_Wk1tlo[HEADS * EMB * 64];
__device__ __align__(16) bf g_Wk2thi[HEADS * HID * 64], g_Wk2tlo[HEADS * HID * 64];
__device__ __align__(16) bf g_A1hi[(size_t)N1 * EMB], g_A1lo[(size_t)N1 * EMB];
__device__ __align__(16) bf g_A2hi[(size_t)NB_B * EMB], g_A2lo[(size_t)NB_B * EMB];
__device__ __align__(16) float g_s1[(size_t)N1 * HID];
__device__ __align__(16) bf g_q1hi[(size_t)N1 * HID];
__device__ __align__(16) bf g_u1[(size_t)N1 * HEADS * EMB];
__device__ __align__(16) bf g_m1hi[(size_t)N1 * HEADS * EMB], g_m1lo[(size_t)N1 * HEADS * EMB];
__device__ __align__(16) float g_h1[(size_t)N1 * HID];
__device__ __align__(16) float g_s2[(size_t)NB_B * HID];
__device__ __align__(16) bf g_q2hi[(size_t)NB_B * HID];
__device__ __align__(16) bf g_u2[(size_t)NB_B * HEADS * HID];
__device__ __align__(16) bf g_m2hi[(size_t)NB_B * HEADS * HID], g_m2lo[(size_t)NB_B * HEADS * HID];

// ---------------- helpers ----------------
__device__ __forceinline__ uint32_t smem_u32(const void* p) {
    uint32_t a;
    asm("{ .reg .u64 t; cvta.to.shared.u64 t, %1; cvt.u32.u64 %0, t; }" : "=r"(a) : "l"(p));
    return a;
}
__device__ __forceinline__ void cp16(uint32_t s, const void* g) {
    asm volatile("cp.async.cg.shared.global [%0], [%1], 16;" :: "r"(s), "l"(g));
}
__device__ __forceinline__ void cp_commit() { asm volatile("cp.async.commit_group;" ::: "memory"); }
__device__ __forceinline__ void cp_wait2() { asm volatile("cp.async.wait_group 2;" ::: "memory"); }
__device__ __forceinline__ void ldmA(uint32_t* a, uint32_t addr) {
    asm volatile("ldmatrix.sync.aligned.m8n8.x4.shared.b16 {%0,%1,%2,%3}, [%4];"
                 : "=r"(a[0]), "=r"(a[1]), "=r"(a[2]), "=r"(a[3]) : "r"(addr));
}
__device__ __forceinline__ void ldmB4(uint32_t* b, uint32_t addr) {
    asm volatile("ldmatrix.sync.aligned.m8n8.x4.shared.b16 {%0,%1,%2,%3}, [%4];"
                 : "=r"(b[0]), "=r"(b[1]), "=r"(b[2]), "=r"(b[3]) : "r"(addr));
}
__device__ __forceinline__ void mma16816(float* d, const uint32_t* a, const uint32_t* b) {
    asm volatile("mma.sync.aligned.m16n8k16.row.col.f32.bf16.bf16.f32 "
                 "{%0,%1,%2,%3}, {%4,%5,%6,%7}, {%8,%9}, {%0,%1,%2,%3};"
                 : "+f"(d[0]), "+f"(d[1]), "+f"(d[2]), "+f"(d[3])
                 : "r"(a[0]), "r"(a[1]), "r"(a[2]), "r"(a[3]), "r"(b[0]), "r"(b[1]));
}

// ---------------- index conversion ----------------
__global__ void convert_idx(const void* sv, const void* n1v, const void* n2v) {
    const unsigned long long* p = (const unsigned long long*)sv;
    bool is64 = (((p[0] | p[1] | p[2] | p[3]) >> 32) == 0ULL);
    int t = blockIdx.x * blockDim.x + threadIdx.x;
    int stride = gridDim.x * blockDim.x;
    if (is64) {
        const long long* a = (const long long*)sv;
        const long long* b = (const long long*)n1v;
        const long long* c = (const long long*)n2v;
        if (t < NB_B) g_seeds[t] = (int)a[t];
        if (t < N1)   g_nbr1[t]  = (int)b[t];
        for (int i = t; i < N2; i += stride) g_nbr2[i] = (int)c[i];
    } else {
        const int* a = (const int*)sv;
        const int* b = (const int*)n1v;
        const int* c = (const int*)n2v;
        if (t < NB_B) g_seeds[t] = a[t];
        if (t < N1)   g_nbr1[t]  = b[t];
        for (int i = t; i < N2; i += stride) g_nbr2[i] = c[i];
    }
}

// ---------------- splits ----------------
__device__ __forceinline__ void split4(float4 x, __nv_bfloat162* hp, __nv_bfloat162* lp) {
    bf h0 = __float2bfloat16(x.x), h1 = __float2bfloat16(x.y);
    bf h2 = __float2bfloat16(x.z), h3 = __float2bfloat16(x.w);
    __nv_bfloat162 H0; H0.x = h0; H0.y = h1;
    __nv_bfloat162 H1; H1.x = h2; H1.y = h3;
    __nv_bfloat162 L0, L1;
    L0.x = __float2bfloat16(x.x - __bfloat162float(h0));
    L0.y = __float2bfloat16(x.y - __bfloat162float(h1));
    L1.x = __float2bfloat16(x.z - __bfloat162float(h2));
    L1.y = __float2bfloat16(x.w - __bfloat162float(h3));
    hp[0] = H0; hp[1] = H1; lp[0] = L0; lp[1] = L1;
}

// all weight preps in ONE kernel. y: 0..5 = wsplit jobs, 6/7 = tsplit Wk1/Wk2.
__global__ void prep_all(const float* __restrict__ Ws1, const float* __restrict__ Wq1,
                         const float* __restrict__ Ws2, const float* __restrict__ Wq2,
                         const float* __restrict__ Wv1, const float* __restrict__ Wv2,
                         const float* __restrict__ Wk1, const float* __restrict__ Wk2) {
    int y = blockIdx.y, bx = blockIdx.x, tid = threadIdx.x;
    if (y < 6) {
        const float* src; bf *hi, *lo; int n4;
        switch (y) {
            case 0: src = Ws1; hi = g_Bs1hi; lo = g_Bs1lo; n4 = W4; break;
            case 1: src = Wq1; hi = g_Bq1hi; lo = g_Bq1lo; n4 = W4; break;
            case 2: src = Ws2; hi = g_B2chi; lo = g_B2clo; n4 = W4; break;
            case 3: src = Wq2; hi = g_B2chi + (size_t)HID * EMB; lo = g_B2clo + (size_t)HID * EMB; n4 = W4; break;
            case 4: src = Wv1; hi = g_Wv1hi; lo = g_Wv1lo; n4 = W4; break;
            default: src = Wv2; hi = g_Wv2hi; lo = g_Wv2lo; n4 = 2 * W4; break;
        }
        int i = bx * 256 + tid;
        if (i < n4)
            split4(((const float4*)src)[i], (__nv_bfloat162*)hi + 2 * i, (__nv_bfloat162*)lo + 2 * i);
    } else {
        __shared__ float tile[64][33];
        const float* src = (y == 6) ? Wk1 : Wk2;
        bf* hi = (y == 6) ? g_Wk1thi : g_Wk2thi;
        bf* lo = (y == 6) ? g_Wk1tlo : g_Wk2tlo;
        int Ecols = (y == 6) ? EMB : HID;
        int ntiles = HEADS * (Ecols / 32);
        if (bx >= ntiles) return;
        int h = bx / (Ecols / 32), e0 = (bx % (Ecols / 32)) * 32;
        int tx = tid & 31, ty = tid >> 5;  // 32 x 8
#pragma unroll
        for (int j = 0; j < 8; j++) {
            int d = ty + 8 * j;
            tile[d][tx] = src[(size_t)(h * 64 + d) * Ecols + e0 + tx];
        }
        __syncthreads();
#pragma unroll
        for (int j = 0; j < 4; j++) {
            int e = ty + 8 * j;
            size_t o = (size_t)(h * Ecols + e0 + e) * 64;
            float x0 = tile[tx][e], x1 = tile[tx + 32][e];
            bf h0 = __float2bfloat16(x0), h1 = __float2bfloat16(x1);
            hi[o + tx] = h0; hi[o + tx + 32] = h1;
            lo[o + tx] = __float2bfloat16(x0 - __bfloat162float(h0));
            lo[o + tx + 32] = __float2bfloat16(x1 - __bfloat162float(h1));
        }
    }
}

// both embedding gathers in one kernel. y=0: A1 via nbr1 (N1 rows), y=1: A2 via seeds.
__global__ void gsplit_all(const float* __restrict__ emb) {
    int y = blockIdx.y;
    int i = blockIdx.x * 256 + threadIdx.x;
    if (y == 0) {
        if (i < N1 * 64) {
            int r = i >> 6, c = i & 63;
            float4 x = ((const float4*)(emb + (size_t)g_nbr1[r] * EMB))[c];
            split4(x, (__nv_bfloat162*)g_A1hi + 2 * i, (__nv_bfloat162*)g_A1lo + 2 * i);
        }
    } else {
        if (i < NB_B * 64) {
            int r = i >> 6, c = i & 63;
            float4 x = ((const float4*)(emb + (size_t)g_seeds[r] * EMB))[c];
            split4(x, (__nv_bfloat162*)g_A2hi + 2 * i, (__nv_bfloat162*)g_A2lo + 2 * i);
        }
    }
}

// ---------------- 4-stage cp.async mma GEMM: C = A @ B^T ----------------
// K-chunk 64 (128B rows), XOR swizzle, warp tile 32x32, dynamic smem 96KB, 1 sync/chunk.
// npass: 3 = hi/lo cross-terms, 1 = hi only.
// modes: 0 fp32 C; 1 relu(acc+E) fp32; 2 bf16 Chi; 3 col<nsplit ? fp32 C : bf16 Chi (col-nsplit).
__global__ __launch_bounds__(256, 2) void mma_gemm(
    float* __restrict__ C, bf* __restrict__ Chi, int ldc, int coffz,
    const float* __restrict__ E, int lde, int eoffz, int mode, int nsplit, int npass,
    const bf* __restrict__ Ahi, const bf* __restrict__ Alo, int lda, int aoffz,
    const bf* __restrict__ Bhi, const bf* __restrict__ Blo, int ldb, int bz,
    int K)
{
    extern __shared__ __align__(16) char dynsm[];
    const uint32_t asb = smem_u32(dynsm);            // 4 x 16KB A
    const uint32_t bsb = asb + 65536u;               // 4 x 8KB B
    const int tid = threadIdx.x, lane = tid & 31, wid = tid >> 5;
    const int z = blockIdx.z, m0 = blockIdx.y * 128, n0 = blockIdx.x * 64;
    const int wm = wid & 3, wn = wid >> 2;
    const int aoff = z * aoffz;
    const bf* Bh = Bhi + (size_t)z * bz;
    const bf* Bl = Blo ? (Blo + (size_t)z * bz) : Bh;
    const int kc = K >> 6, nch = npass * kc;

    const int lr = tid >> 3;
    const int lch = tid & 7;
    const uint32_t lsw = (uint32_t)((lch ^ (lr & 7)) * 16);

    auto issue = [&](int c) {
        int pass = c / kc, k0 = (c - pass * kc) << 6;
        const bf* Ap = (pass == 2) ? Alo : Ahi;
        const bf* Bp = (pass == 1) ? Bl : Bh;
        int buf = c & 3;
        uint32_t sa = asb + buf * 16384u, sb = bsb + buf * 8192u;
#pragma unroll
        for (int i = 0; i < 4; i++) {
            int rr = lr + 32 * i;
            cp16(sa + rr * 128 + lsw, Ap + (size_t)(m0 + rr) * lda + aoff + k0 + lch * 8);
        }
#pragma unroll
        for (int i = 0; i < 2; i++) {
            int rr = lr + 32 * i;
            cp16(sb + rr * 128 + lsw, Bp + (size_t)(n0 + rr) * ldb + k0 + lch * 8);
        }
        cp_commit();
    };

    float acc[2][4][4];
#pragma unroll
    for (int i = 0; i < 2; i++)
#pragma unroll
        for (int j = 0; j < 4; j++)
#pragma unroll
            for (int k = 0; k < 4; k++) acc[i][j][k] = 0.f;

#pragma unroll
    for (int c = 0; c < 3; c++) { if (c < nch) issue(c); else cp_commit(); }

    for (int i = 0; i < nch; i++) {
        cp_wait2();
        __syncthreads();
        if (i + 3 < nch) issue(i + 3); else cp_commit();
        uint32_t ab = asb + (i & 3) * 16384u;
        uint32_t bb = bsb + (i & 3) * 8192u;
#pragma unroll
        for (int s = 0; s < 4; s++) {
            uint32_t bq[2][4];
#pragma unroll
            for (int np = 0; np < 2; np++) {
                int g = lane >> 3;
                int brow = wn * 32 + np * 16 + (g >> 1) * 8 + (lane & 7);
                int bch = s * 2 + (g & 1);
                ldmB4(bq[np], bb + brow * 128 + ((bch ^ (brow & 7)) * 16));
            }
#pragma unroll
            for (int mi = 0; mi < 2; mi++) {
                int arow = wm * 32 + mi * 16 + (lane & 15);
                int ach = s * 2 + (lane >> 4);
                uint32_t afr[4];
                ldmA(afr, ab + arow * 128 + ((ach ^ (arow & 7)) * 16));
#pragma unroll
                for (int ni = 0; ni < 4; ni++)
                    mma16816(acc[mi][ni], afr, &bq[ni >> 1][(ni & 1) * 2]);
            }
        }
    }

    const int r0 = lane >> 2, cp = (lane & 3) * 2;
#pragma unroll
    for (int mi = 0; mi < 2; mi++) {
#pragma unroll
        for (int half = 0; half < 2; half++) {
            int row = m0 + wm * 32 + mi * 16 + r0 + half * 8;
#pragma unroll
            for (int ni = 0; ni < 4; ni++) {
                int col = n0 + wn * 32 + ni * 8 + cp;
                float v0 = acc[mi][ni][half * 2 + 0];
                float v1 = acc[mi][ni][half * 2 + 1];
                bool qside = (mode == 2) || (mode == 3 && col >= nsplit);
                if (mode == 1) {
                    size_t off = (size_t)row * ldc + z * coffz + col;
                    size_t eo = (size_t)row * lde + z * eoffz + col;
                    float2 ev = *(const float2*)(E + eo);
                    float2 o;
                    o.x = fmaxf(v0 + ev.x, 0.f);
                    o.y = fmaxf(v1 + ev.y, 0.f);
                    *(float2*)(C + off) = o;
                } else if (qside) {
                    size_t off = (size_t)row * ldc + z * coffz + (col - nsplit);
                    __nv_bfloat162 hh;
                    hh.x = __float2bfloat16(v0);
                    hh.y = __float2bfloat16(v1);
                    *(__nv_bfloat162*)(Chi + off) = hh;
                } else {
                    size_t off = (size_t)row * ldc + z * coffz + col;
                    float2 o; o.x = v0; o.y = v1;
                    *(float2*)(C + off) = o;
                }
            }
        }
    }
}

// ---------------- fused attention layer 1 (u in bf16) ----------------
__global__ __launch_bounds__(256) void attn1_kernel(const float* __restrict__ emb) {
    __shared__ float sh2[FAN_2][EMB];
    int n = blockIdx.x, tid = threadIdx.x;
    for (int i = tid; i < FAN_2 * 64; i += 256) {
        int f = i >> 6, c = i & 63;
        ((float4*)sh2[f])[c] = ((const float4*)(emb + (size_t)g_nbr2[n * FAN_2 + f] * EMB))[c];
    }
    int w = tid >> 5, l = tid & 31;
    const bf* up = g_u1 + (size_t)n * (HEADS * EMB) + w * EMB;
    float u[8];
#pragma unroll
    for (int j = 0; j < 8; j++) u[j] = __bfloat162float(up[l + j * 32]);
    __syncthreads();

    float at[FAN_2], mx = -1e30f;
#pragma unroll
    for (int f = 0; f < FAN_2; f++) {
        float p = 0.f;
#pragma unroll
        for (int j = 0; j < 8; j++) p += sh2[f][l + j * 32] * u[j];
#pragma unroll
        for (int o = 16; o; o >>= 1) p += __shfl_xor_sync(0xffffffffu, p, o);
        p *= 0.125f;
        at[f] = p; mx = fmaxf(mx, p);
    }
    float s = 0.f;
#pragma unroll
    for (int f = 0; f < FAN_2; f++) { at[f] = expf(at[f] - mx); s += at[f]; }
    float inv = 1.f / s;
    size_t mo = (size_t)n * (HEADS * EMB) + w * EMB;
#pragma unroll
    for (int j = 0; j < 8; j++) {
        int e = l + j * 32;
        float m = 0.f;
#pragma unroll
        for (int f = 0; f < FAN_2; f++) m += at[f] * sh2[f][e];
        m *= inv;
        bf h = __float2bfloat16(m);
        g_m1hi[mo + e] = h;
        g_m1lo[mo + e] = __float2bfloat16(m - __bfloat162float(h));
    }
}

// ---------------- fused attention layer 2 (u in bf16) ----------------
__global__ __launch_bounds__(256) void attn2_kernel() {
    __shared__ float sh1[FAN_1][HID];
    int b = blockIdx.x, tid = threadIdx.x;
    const float4* hp = (const float4*)(g_h1 + (size_t)b * FAN_1 * HID);
    for (int i = tid; i < FAN_1 * HID / 4; i += 256) ((float4*)&sh1[0][0])[i] = hp[i];
    int w = tid >> 5, l = tid & 31;
    const bf* up = g_u2 + (size_t)b * (HEADS * HID) + w * HID;
    float u[16];
#pragma unroll
    for (int j = 0; j < 16; j++) u[j] = __bfloat162float(up[l + j * 32]);
    __syncthreads();

    float at[FAN_1], mx = -1e30f;
#pragma unroll
    for (int f = 0; f < FAN_1; f++) {
        float p = 0.f;
#pragma unroll
        for (int j = 0; j < 16; j++) p += sh1[f][l + j * 32] * u[j];
#pragma unroll
        for (int o = 16; o; o >>= 1) p += __shfl_xor_sync(0xffffffffu, p, o);
        p *= 0.125f;
        at[f] = p; mx = fmaxf(mx, p);
    }
    float s = 0.f;
#pragma unroll
    for (int f = 0; f < FAN_1; f++) { at[f] = expf(at[f] - mx); s += at[f]; }
    float inv = 1.f / s;
    size_t mo = (size_t)b * (HEADS * HID) + w * HID;
#pragma unroll
    for (int j = 0; j < 16; j++) {
        int e = l + j * 32;
        float m = 0.f;
#pragma unroll
        for (int f = 0; f < FAN_1; f++) m += at[f] * sh1[f][e];
        m *= inv;
        bf h = __float2bfloat16(m);
        g_m2hi[mo + e] = h;
        g_m2lo[mo + e] = __float2bfloat16(m - __bfloat162float(h));
    }
}

// ---------------- host ----------------
#define GET(n) void* p_##n; cudaGetSymbolAddress(&p_##n, g_##n)
#define DSM 98304

extern "C" void kernel_launch(void* const* d_in, const int* in_sizes, int n_in,
                              void* d_out, int out_size) {
    const void* seeds = d_in[0];
    const void* nbr1  = d_in[1];
    const void* nbr2  = d_in[2];
    const float* emb = (const float*)d_in[3];
    const float* Wq1 = (const float*)d_in[4];
    const float* Wk1 = (const float*)d_in[5];
    const float* Wv1 = (const float*)d_in[6];
    const float* Ws1 = (const float*)d_in[7];
    const float* Wq2 = (const float*)d_in[8];
    const float* Wk2 = (const float*)d_in[9];
    const float* Wv2 = (const float*)d_in[10];
    const float* Ws2 = (const float*)d_in[11];
    float* out = (float*)d_out;

    GET(Bs1hi); GET(Bs1lo); GET(Bq1hi); GET(Bq1lo);
    GET(B2chi); GET(B2clo);
    GET(Wv1hi); GET(Wv1lo); GET(Wv2hi); GET(Wv2lo);
    GET(Wk1thi); GET(Wk1tlo); GET(Wk2thi); GET(Wk2tlo);
    GET(A1hi); GET(A1lo); GET(A2hi); GET(A2lo);
    GET(s1); GET(q1hi); GET(u1); GET(m1hi); GET(m1lo); GET(h1);
    GET(s2); GET(q2hi); GET(u2); GET(m2hi); GET(m2lo);

    cudaFuncSetAttribute(mma_gemm, cudaFuncAttributeMaxDynamicSharedMemorySize, DSM);

    // 0: indices
    convert_idx<<<600, 256>>>(seeds, nbr1, nbr2);
    // 1: all weight splits + transposes
    prep_all<<<dim3(256, 8), 256>>>(Ws1, Wq1, Ws2, Wq2, Wv1, Wv2, Wk1, Wk2);
    // 2: both embedding gathers
    gsplit_all<<<dim3(N1 * 64 / 256, 2), 256>>>(emb);
    // 3: s1 = A1 @ Ws1^T (3-pass fp32)  <-- profiled launch
    mma_gemm<<<dim3(8, 120, 1), 256, DSM>>>(
        (float*)p_s1, nullptr, HID, 0, nullptr, 0, 0, 0, 0, 3,
        (bf*)p_A1hi, (bf*)p_A1lo, EMB, 0, (bf*)p_Bs1hi, (bf*)p_Bs1lo, EMB, 0, EMB);
    // 4: q1 = A1 @ Wq1^T (1-pass, bf16)
    mma_gemm<<<dim3(8, 120, 1), 256, DSM>>>(
        nullptr, (bf*)p_q1hi, HID, 0, nullptr, 0, 0, 2, 0, 1,
        (bf*)p_A1hi, (bf*)p_A1hi, EMB, 0, (bf*)p_Bq1hi, nullptr, EMB, 0, EMB);
    // 5: u1 = q1_h @ Wk1t_h^T (1-pass, bf16), K=64
    mma_gemm<<<dim3(4, 120, 8), 256, DSM>>>(
        nullptr, (bf*)p_u1, HEADS * EMB, EMB, nullptr, 0, 0, 2, 0, 1,
        (bf*)p_q1hi, (bf*)p_q1hi, HID, 64, (bf*)p_Wk1thi, nullptr, 64, EMB * 64, 64);
    // 6: attention layer 1
    attn1_kernel<<<N1, 256>>>(emb);
    // 7: h1 = relu(s1 + m1_h @ Wv1_h^T) (3-pass)
    mma_gemm<<<dim3(1, 120, 8), 256, DSM>>>(
        (float*)p_h1, nullptr, HID, 64, (const float*)p_s1, HID, 64, 1, 0, 3,
        (bf*)p_m1hi, (bf*)p_m1lo, HEADS * EMB, EMB, (bf*)p_Wv1hi, (bf*)p_Wv1lo, EMB, 64 * EMB, EMB);
    // 8: [s2 | q2] = A2 @ [Ws2;Wq2]^T (3-pass, split epilogue)
    mma_gemm<<<dim3(16, 8, 1), 256, DSM>>>(
        (float*)p_s2, (bf*)p_q2hi, HID, 0, nullptr, 0, 0, 3, HID, 3,
        (bf*)p_A2hi, (bf*)p_A2lo, EMB, 0, (bf*)p_B2chi, (bf*)p_B2clo, EMB, 0, EMB);
    // 9: u2 = q2_h @ Wk2t_h^T (1-pass, bf16), K=64
    mma_gemm<<<dim3(8, 8, 8), 256, DSM>>>(
        nullptr, (bf*)p_u2, HEADS * HID, HID, nullptr, 0, 0, 2, 0, 1,
        (bf*)p_q2hi, (bf*)p_q2hi, HID, 64, (bf*)p_Wk2thi, nullptr, 64, HID * 64, 64);
    // 10: attention layer 2
    attn2_kernel<<<NB_B, 256>>>();
    // 11: out = relu(s2 + m2_h @ Wv2_h^T) (3-pass), K=512
    mma_gemm<<<dim3(1, 8, 8), 256, DSM>>>(
        out, nullptr, HID, 64, (const float*)p_s2, HID, 64, 1, 0, 3,
        (bf*)p_m2hi, (bf*)p_m2lo, HEADS * HID, HID, (bf*)p_Wv2hi, (bf*)p_Wv2lo, HID, 64 * HID, HID);
}

// round 13
// speedup vs baseline: 1.0756x; 1.0756x over previous
#include <cuda_runtime.h>
#include <cuda_bf16.h>
#include <cstdint>

#define NB_B 1024
#define FAN_1 15
#define FAN_2 10
#define EMB 256
#define HID 512
#define HEADS 8
#define N1 (NB_B * FAN_1)
#define N2 (N1 * FAN_2)
#define W4 (HID * EMB / 4)

typedef __nv_bfloat16 bf;

// ---------------- scratch (16B-aligned for cp.async) ----------------
__device__ int g_seeds[NB_B];
__device__ int g_nbr1[N1];
__device__ int g_nbr2[N2];
__device__ __align__(16) bf g_Bs1hi[HID * EMB], g_Bs1lo[HID * EMB];
__device__ __align__(16) bf g_Bq1hi[HID * EMB], g_Bq1lo[HID * EMB];
__device__ __align__(16) bf g_B2chi[2 * HID * EMB], g_B2clo[2 * HID * EMB];  // [Ws2;Wq2]
__device__ __align__(16) bf g_Wv1hi[HID * EMB], g_Wv1lo[HID * EMB];
__device__ __align__(16) bf g_Wv2hi[HID * HID], g_Wv2lo[HID * HID];
__device__ __align__(16) bf g_Wk1thi[HEADS * EMB * 64], g_Wk1tlo[HEADS * EMB * 64];
__device__ __align__(16) bf g_Wk2thi[HEADS * HID * 64], g_Wk2tlo[HEADS * HID * 64];
__device__ __align__(16) bf g_A1hi[(size_t)N1 * EMB], g_A1lo[(size_t)N1 * EMB];
__device__ __align__(16) bf g_A2hi[(size_t)NB_B * EMB], g_A2lo[(size_t)NB_B * EMB];
__device__ __align__(16) float g_s1[(size_t)N1 * HID];
__device__ __align__(16) bf g_q1hi[(size_t)N1 * HID];
__device__ __align__(16) bf g_u1[(size_t)N1 * HEADS * EMB];
__device__ __align__(16) bf g_m1hi[(size_t)N1 * HEADS * EMB], g_m1lo[(size_t)N1 * HEADS * EMB];
__device__ __align__(16) float g_h1[(size_t)N1 * HID];
__device__ __align__(16) float g_s2[(size_t)NB_B * HID];
__device__ __align__(16) bf g_q2hi[(size_t)NB_B * HID];
__device__ __align__(16) bf g_u2[(size_t)NB_B * HEADS * HID];
__device__ __align__(16) bf g_m2hi[(size_t)NB_B * HEADS * HID], g_m2lo[(size_t)NB_B * HEADS * HID];

// ---------------- helpers ----------------
__device__ __forceinline__ uint32_t smem_u32(const void* p) {
    uint32_t a;
    asm("{ .reg .u64 t; cvta.to.shared.u64 t, %1; cvt.u32.u64 %0, t; }" : "=r"(a) : "l"(p));
    return a;
}
__device__ __forceinline__ void cp16(uint32_t s, const void* g) {
    asm volatile("cp.async.cg.shared.global [%0], [%1], 16;" :: "r"(s), "l"(g));
}
__device__ __forceinline__ void cp_commit() { asm volatile("cp.async.commit_group;" ::: "memory"); }
__device__ __forceinline__ void cp_wait1() { asm volatile("cp.async.wait_group 1;" ::: "memory"); }
__device__ __forceinline__ void ldmA(uint32_t* a, uint32_t addr) {
    asm volatile("ldmatrix.sync.aligned.m8n8.x4.shared.b16 {%0,%1,%2,%3}, [%4];"
                 : "=r"(a[0]), "=r"(a[1]), "=r"(a[2]), "=r"(a[3]) : "r"(addr));
}
__device__ __forceinline__ void ldmB4(uint32_t* b, uint32_t addr) {
    asm volatile("ldmatrix.sync.aligned.m8n8.x4.shared.b16 {%0,%1,%2,%3}, [%4];"
                 : "=r"(b[0]), "=r"(b[1]), "=r"(b[2]), "=r"(b[3]) : "r"(addr));
}
__device__ __forceinline__ void mma16816(float* d, const uint32_t* a, const uint32_t* b) {
    asm volatile("mma.sync.aligned.m16n8k16.row.col.f32.bf16.bf16.f32 "
                 "{%0,%1,%2,%3}, {%4,%5,%6,%7}, {%8,%9}, {%0,%1,%2,%3};"
                 : "+f"(d[0]), "+f"(d[1]), "+f"(d[2]), "+f"(d[3])
                 : "r"(a[0]), "r"(a[1]), "r"(a[2]), "r"(a[3]), "r"(b[0]), "r"(b[1]));
}

// ---------------- index conversion ----------------
__global__ void convert_idx(const void* sv, const void* n1v, const void* n2v) {
    const unsigned long long* p = (const unsigned long long*)sv;
    bool is64 = (((p[0] | p[1] | p[2] | p[3]) >> 32) == 0ULL);
    int t = blockIdx.x * blockDim.x + threadIdx.x;
    int stride = gridDim.x * blockDim.x;
    if (is64) {
        const long long* a = (const long long*)sv;
        const long long* b = (const long long*)n1v;
        const long long* c = (const long long*)n2v;
        if (t < NB_B) g_seeds[t] = (int)a[t];
        if (t < N1)   g_nbr1[t]  = (int)b[t];
        for (int i = t; i < N2; i += stride) g_nbr2[i] = (int)c[i];
    } else {
        const int* a = (const int*)sv;
        const int* b = (const int*)n1v;
        const int* c = (const int*)n2v;
        if (t < NB_B) g_seeds[t] = a[t];
        if (t < N1)   g_nbr1[t]  = b[t];
        for (int i = t; i < N2; i += stride) g_nbr2[i] = c[i];
    }
}

// ---------------- splits ----------------
__device__ __forceinline__ void split4(float4 x, __nv_bfloat162* hp, __nv_bfloat162* lp) {
    bf h0 = __float2bfloat16(x.x), h1 = __float2bfloat16(x.y);
    bf h2 = __float2bfloat16(x.z), h3 = __float2bfloat16(x.w);
    __nv_bfloat162 H0; H0.x = h0; H0.y = h1;
    __nv_bfloat162 H1; H1.x = h2; H1.y = h3;
    __nv_bfloat162 L0, L1;
    L0.x = __float2bfloat16(x.x - __bfloat162float(h0));
    L0.y = __float2bfloat16(x.y - __bfloat162float(h1));
    L1.x = __float2bfloat16(x.z - __bfloat162float(h2));
    L1.y = __float2bfloat16(x.w - __bfloat162float(h3));
    hp[0] = H0; hp[1] = H1; lp[0] = L0; lp[1] = L1;
}

// all weight preps in ONE kernel. y: 0..5 = wsplit jobs, 6/7 = tsplit Wk1/Wk2.
__global__ void prep_all(const float* __restrict__ Ws1, const float* __restrict__ Wq1,
                         const float* __restrict__ Ws2, const float* __restrict__ Wq2,
                         const float* __restrict__ Wv1, const float* __restrict__ Wv2,
                         const float* __restrict__ Wk1, const float* __restrict__ Wk2) {
    int y = blockIdx.y, bx = blockIdx.x, tid = threadIdx.x;
    if (y < 6) {
        const float* src; bf *hi, *lo; int n4;
        switch (y) {
            case 0: src = Ws1; hi = g_Bs1hi; lo = g_Bs1lo; n4 = W4; break;
            case 1: src = Wq1; hi = g_Bq1hi; lo = g_Bq1lo; n4 = W4; break;
            case 2: src = Ws2; hi = g_B2chi; lo = g_B2clo; n4 = W4; break;
            case 3: src = Wq2; hi = g_B2chi + (size_t)HID * EMB; lo = g_B2clo + (size_t)HID * EMB; n4 = W4; break;
            case 4: src = Wv1; hi = g_Wv1hi; lo = g_Wv1lo; n4 = W4; break;
            default: src = Wv2; hi = g_Wv2hi; lo = g_Wv2lo; n4 = 2 * W4; break;
        }
        int i = bx * 256 + tid;
        if (i < n4)
            split4(((const float4*)src)[i], (__nv_bfloat162*)hi + 2 * i, (__nv_bfloat162*)lo + 2 * i);
    } else {
        __shared__ float tile[64][33];
        const float* src = (y == 6) ? Wk1 : Wk2;
        bf* hi = (y == 6) ? g_Wk1thi : g_Wk2thi;
        bf* lo = (y == 6) ? g_Wk1tlo : g_Wk2tlo;
        int Ecols = (y == 6) ? EMB : HID;
        int ntiles = HEADS * (Ecols / 32);
        if (bx >= ntiles) return;
        int h = bx / (Ecols / 32), e0 = (bx % (Ecols / 32)) * 32;
        int tx = tid & 31, ty = tid >> 5;  // 32 x 8
#pragma unroll
        for (int j = 0; j < 8; j++) {
            int d = ty + 8 * j;
            tile[d][tx] = src[(size_t)(h * 64 + d) * Ecols + e0 + tx];
        }
        __syncthreads();
#pragma unroll
        for (int j = 0; j < 4; j++) {
            int e = ty + 8 * j;
            size_t o = (size_t)(h * Ecols + e0 + e) * 64;
            float x0 = tile[tx][e], x1 = tile[tx + 32][e];
            bf h0 = __float2bfloat16(x0), h1 = __float2bfloat16(x1);
            hi[o + tx] = h0; hi[o + tx + 32] = h1;
            lo[o + tx] = __float2bfloat16(x0 - __bfloat162float(h0));
            lo[o + tx + 32] = __float2bfloat16(x1 - __bfloat162float(h1));
        }
    }
}

// both embedding gathers in one kernel. y=0: A1 via nbr1 (N1 rows), y=1: A2 via seeds.
__global__ void gsplit_all(const float* __restrict__ emb) {
    int y = blockIdx.y;
    int i = blockIdx.x * 256 + threadIdx.x;
    if (y == 0) {
        if (i < N1 * 64) {
            int r = i >> 6, c = i & 63;
            float4 x = ((const float4*)(emb + (size_t)g_nbr1[r] * EMB))[c];
            split4(x, (__nv_bfloat162*)g_A1hi + 2 * i, (__nv_bfloat162*)g_A1lo + 2 * i);
        }
    } else {
        if (i < NB_B * 64) {
            int r = i >> 6, c = i & 63;
            float4 x = ((const float4*)(emb + (size_t)g_seeds[r] * EMB))[c];
            split4(x, (__nv_bfloat162*)g_A2hi + 2 * i, (__nv_bfloat162*)g_A2lo + 2 * i);
        }
    }
}

// ---------------- 2-stage cp.async mma GEMM: C = A @ B^T, block 128 x BN ----------------
// K-chunk 64 (128B rows), XOR swizzle, warp tile 32 x (BN/2).
// npass: 3 = hi/lo cross-terms, 1 = hi only.
// modes: 0 fp32 C; 1 relu(acc+E) fp32; 2 bf16 Chi; 3 col<nsplit ? fp32 C : bf16 Chi (col-nsplit).
template <int BN>
__global__ __launch_bounds__(256, 2) void mma_gemm(
    float* __restrict__ C, bf* __restrict__ Chi, int ldc, int coffz,
    const float* __restrict__ E, int lde, int eoffz, int mode, int nsplit, int npass,
    const bf* __restrict__ Ahi, const bf* __restrict__ Alo, int lda, int aoffz,
    const bf* __restrict__ Bhi, const bf* __restrict__ Blo, int ldb, int bz,
    int K)
{
    extern __shared__ __align__(16) char dynsm[];
    constexpr int NI = BN / 16;       // n-frags per warp (8 or 4)
    constexpr int NP = BN / 32;       // ldmB4 per s-step / B load iters
    constexpr uint32_t BSTRIDE = BN * 128;
    const uint32_t asb = smem_u32(dynsm);            // 2 x 16KB A
    const uint32_t bsb = asb + 32768u;               // 2 x BN*128 B
    const int tid = threadIdx.x, lane = tid & 31, wid = tid >> 5;
    const int z = blockIdx.z, m0 = blockIdx.y * 128, n0 = blockIdx.x * BN;
    const int wm = wid & 3, wn = wid >> 2;           // 4(m) x 2(n)
    const int aoff = z * aoffz;
    const bf* Bh = Bhi + (size_t)z * bz;
    const bf* Bl = Blo ? (Blo + (size_t)z * bz) : Bh;
    const int kc = K >> 6, nch = npass * kc;

    const int lr = tid >> 3;
    const int lch = tid & 7;
    const uint32_t lsw = (uint32_t)((lch ^ (lr & 7)) * 16);

    auto issue = [&](int c) {
        int pass = c / kc, k0 = (c - pass * kc) << 6;
        const bf* Ap = (pass == 2) ? Alo : Ahi;
        const bf* Bp = (pass == 1) ? Bl : Bh;
        int buf = c & 1;
        uint32_t sa = asb + buf * 16384u, sb = bsb + buf * BSTRIDE;
#pragma unroll
        for (int i = 0; i < 4; i++) {
            int rr = lr + 32 * i;
            cp16(sa + rr * 128 + lsw, Ap + (size_t)(m0 + rr) * lda + aoff + k0 + lch * 8);
        }
#pragma unroll
        for (int i = 0; i < NP; i++) {
            int rr = lr + 32 * i;
            cp16(sb + rr * 128 + lsw, Bp + (size_t)(n0 + rr) * ldb + k0 + lch * 8);
        }
        cp_commit();
    };

    float acc[2][NI][4];
#pragma unroll
    for (int i = 0; i < 2; i++)
#pragma unroll
        for (int j = 0; j < NI; j++)
#pragma unroll
            for (int k = 0; k < 4; k++) acc[i][j][k] = 0.f;

    issue(0);
    if (nch > 1) issue(1); else cp_commit();

    for (int i = 0; i < nch; i++) {
        cp_wait1();
        __syncthreads();
        uint32_t ab = asb + (i & 1) * 16384u;
        uint32_t bb = bsb + (i & 1) * BSTRIDE;
#pragma unroll
        for (int s = 0; s < 4; s++) {
            uint32_t bq[NP][4];
#pragma unroll
            for (int np = 0; np < NP; np++) {
                int g = lane >> 3;
                int brow = wn * (BN / 2) + np * 16 + (g >> 1) * 8 + (lane & 7);
                int bch = s * 2 + (g & 1);
                ldmB4(bq[np], bb + brow * 128 + ((bch ^ (brow & 7)) * 16));
            }
#pragma unroll
            for (int mi = 0; mi < 2; mi++) {
                int arow = wm * 32 + mi * 16 + (lane & 15);
                int ach = s * 2 + (lane >> 4);
                uint32_t afr[4];
                ldmA(afr, ab + arow * 128 + ((ach ^ (arow & 7)) * 16));
#pragma unroll
                for (int ni = 0; ni < NI; ni++)
                    mma16816(acc[mi][ni], afr, &bq[ni >> 1][(ni & 1) * 2]);
            }
        }
        __syncthreads();
        if (i + 2 < nch) issue(i + 2); else cp_commit();
    }

    const int r0 = lane >> 2, cp = (lane & 3) * 2;
#pragma unroll
    for (int mi = 0; mi < 2; mi++) {
#pragma unroll
        for (int half = 0; half < 2; half++) {
            int row = m0 + wm * 32 + mi * 16 + r0 + half * 8;
#pragma unroll
            for (int ni = 0; ni < NI; ni++) {
                int col = n0 + wn * (BN / 2) + ni * 8 + cp;
                float v0 = acc[mi][ni][half * 2 + 0];
                float v1 = acc[mi][ni][half * 2 + 1];
                bool qside = (mode == 2) || (mode == 3 && col >= nsplit);
                if (mode == 1) {
                    size_t off = (size_t)row * ldc + z * coffz + col;
                    size_t eo = (size_t)row * lde + z * eoffz + col;
                    float2 ev = *(const float2*)(E + eo);
                    float2 o;
                    o.x = fmaxf(v0 + ev.x, 0.f);
                    o.y = fmaxf(v1 + ev.y, 0.f);
                    *(float2*)(C + off) = o;
                } else if (qside) {
                    size_t off = (size_t)row * ldc + z * coffz + (col - nsplit);
                    __nv_bfloat162 hh;
                    hh.x = __float2bfloat16(v0);
                    hh.y = __float2bfloat16(v1);
                    *(__nv_bfloat162*)(Chi + off) = hh;
                } else {
                    size_t off = (size_t)row * ldc + z * coffz + col;
                    float2 o; o.x = v0; o.y = v1;
                    *(float2*)(C + off) = o;
                }
            }
        }
    }
}

// ---------------- fused attention layer 1 (u in bf16) ----------------
__global__ __launch_bounds__(256) void attn1_kernel(const float* __restrict__ emb) {
    __shared__ float sh2[FAN_2][EMB];
    int n = blockIdx.x, tid = threadIdx.x;
    for (int i = tid; i < FAN_2 * 64; i += 256) {
        int f = i >> 6, c = i & 63;
        ((float4*)sh2[f])[c] = ((const float4*)(emb + (size_t)g_nbr2[n * FAN_2 + f] * EMB))[c];
    }
    int w = tid >> 5, l = tid & 31;
    const bf* up = g_u1 + (size_t)n * (HEADS * EMB) + w * EMB;
    float u[8];
#pragma unroll
    for (int j = 0; j < 8; j++) u[j] = __bfloat162float(up[l + j * 32]);
    __syncthreads();

    float at[FAN_2], mx = -1e30f;
#pragma unroll
    for (int f = 0; f < FAN_2; f++) {
        float p = 0.f;
#pragma unroll
        for (int j = 0; j < 8; j++) p += sh2[f][l + j * 32] * u[j];
#pragma unroll
        for (int o = 16; o; o >>= 1) p += __shfl_xor_sync(0xffffffffu, p, o);
        p *= 0.125f;
        at[f] = p; mx = fmaxf(mx, p);
    }
    float s = 0.f;
#pragma unroll
    for (int f = 0; f < FAN_2; f++) { at[f] = expf(at[f] - mx); s += at[f]; }
    float inv = 1.f / s;
    size_t mo = (size_t)n * (HEADS * EMB) + w * EMB;
#pragma unroll
    for (int j = 0; j < 8; j++) {
        int e = l + j * 32;
        float m = 0.f;
#pragma unroll
        for (int f = 0; f < FAN_2; f++) m += at[f] * sh2[f][e];
        m *= inv;
        bf h = __float2bfloat16(m);
        g_m1hi[mo + e] = h;
        g_m1lo[mo + e] = __float2bfloat16(m - __bfloat162float(h));
    }
}

// ---------------- fused attention layer 2 (u in bf16) ----------------
__global__ __launch_bounds__(256) void attn2_kernel() {
    __shared__ float sh1[FAN_1][HID];
    int b = blockIdx.x, tid = threadIdx.x;
    const float4* hp = (const float4*)(g_h1 + (size_t)b * FAN_1 * HID);
    for (int i = tid; i < FAN_1 * HID / 4; i += 256) ((float4*)&sh1[0][0])[i] = hp[i];
    int w = tid >> 5, l = tid & 31;
    const bf* up = g_u2 + (size_t)b * (HEADS * HID) + w * HID;
    float u[16];
#pragma unroll
    for (int j = 0; j < 16; j++) u[j] = __bfloat162float(up[l + j * 32]);
    __syncthreads();

    float at[FAN_1], mx = -1e30f;
#pragma unroll
    for (int f = 0; f < FAN_1; f++) {
        float p = 0.f;
#pragma unroll
        for (int j = 0; j < 16; j++) p += sh1[f][l + j * 32] * u[j];
#pragma unroll
        for (int o = 16; o; o >>= 1) p += __shfl_xor_sync(0xffffffffu, p, o);
        p *= 0.125f;
        at[f] = p; mx = fmaxf(mx, p);
    }
    float s = 0.f;
#pragma unroll
    for (int f = 0; f < FAN_1; f++) { at[f] = expf(at[f] - mx); s += at[f]; }
    float inv = 1.f / s;
    size_t mo = (size_t)b * (HEADS * HID) + w * HID;
#pragma unroll
    for (int j = 0; j < 16; j++) {
        int e = l + j * 32;
        float m = 0.f;
#pragma unroll
        for (int f = 0; f < FAN_1; f++) m += at[f] * sh1[f][e];
        m *= inv;
        bf h = __float2bfloat16(m);
        g_m2hi[mo + e] = h;
        g_m2lo[mo + e] = __float2bfloat16(m - __bfloat162float(h));
    }
}

// ---------------- host ----------------
#define GET(n) void* p_##n; cudaGetSymbolAddress(&p_##n, g_##n)
#define DSM128 (32768 + 2 * 128 * 128)   /* 65536 */
#define DSM64  (32768 + 2 * 64 * 128)    /* 49152 */

extern "C" void kernel_launch(void* const* d_in, const int* in_sizes, int n_in,
                              void* d_out, int out_size) {
    const void* seeds = d_in[0];
    const void* nbr1  = d_in[1];
    const void* nbr2  = d_in[2];
    const float* emb = (const float*)d_in[3];
    const float* Wq1 = (const float*)d_in[4];
    const float* Wk1 = (const float*)d_in[5];
    const float* Wv1 = (const float*)d_in[6];
    const float* Ws1 = (const float*)d_in[7];
    const float* Wq2 = (const float*)d_in[8];
    const float* Wk2 = (const float*)d_in[9];
    const float* Wv2 = (const float*)d_in[10];
    const float* Ws2 = (const float*)d_in[11];
    float* out = (float*)d_out;

    GET(Bs1hi); GET(Bs1lo); GET(Bq1hi); GET(Bq1lo);
    GET(B2chi); GET(B2clo);
    GET(Wv1hi); GET(Wv1lo); GET(Wv2hi); GET(Wv2lo);
    GET(Wk1thi); GET(Wk1tlo); GET(Wk2thi); GET(Wk2tlo);
    GET(A1hi); GET(A1lo); GET(A2hi); GET(A2lo);
    GET(s1); GET(q1hi); GET(u1); GET(m1hi); GET(m1lo); GET(h1);
    GET(s2); GET(q2hi); GET(u2); GET(m2hi); GET(m2lo);

    cudaFuncSetAttribute(mma_gemm<128>, cudaFuncAttributeMaxDynamicSharedMemorySize, DSM128);
    cudaFuncSetAttribute(mma_gemm<64>,  cudaFuncAttributeMaxDynamicSharedMemorySize, DSM64);

    // 0: indices
    convert_idx<<<600, 256>>>(seeds, nbr1, nbr2);
    // 1: all weight splits + transposes
    prep_all<<<dim3(256, 8), 256>>>(Ws1, Wq1, Ws2, Wq2, Wv1, Wv2, Wk1, Wk2);
    // 2: both embedding gathers
    gsplit_all<<<dim3(N1 * 64 / 256, 2), 256>>>(emb);
    // 3: s1 = A1 @ Ws1^T (3-pass fp32)  <-- profiled launch
    mma_gemm<128><<<dim3(4, 120, 1), 256, DSM128>>>(
        (float*)p_s1, nullptr, HID, 0, nullptr, 0, 0, 0, 0, 3,
        (bf*)p_A1hi, (bf*)p_A1lo, EMB, 0, (bf*)p_Bs1hi, (bf*)p_Bs1lo, EMB, 0, EMB);
    // 4: q1 = A1 @ Wq1^T (1-pass, bf16)
    mma_gemm<128><<<dim3(4, 120, 1), 256, DSM128>>>(
        nullptr, (bf*)p_q1hi, HID, 0, nullptr, 0, 0, 2, 0, 1,
        (bf*)p_A1hi, (bf*)p_A1hi, EMB, 0, (bf*)p_Bq1hi, nullptr, EMB, 0, EMB);
    // 5: u1 = q1_h @ Wk1t_h^T (1-pass, bf16), K=64
    mma_gemm<128><<<dim3(2, 120, 8), 256, DSM128>>>(
        nullptr, (bf*)p_u1, HEADS * EMB, EMB, nullptr, 0, 0, 2, 0, 1,
        (bf*)p_q1hi, (bf*)p_q1hi, HID, 64, (bf*)p_Wk1thi, nullptr, 64, EMB * 64, 64);
    // 6: attention layer 1
    attn1_kernel<<<N1, 256>>>(emb);
    // 7: h1 = relu(s1 + m1_h @ Wv1_h^T) (3-pass), N=64 per head
    mma_gemm<64><<<dim3(1, 120, 8), 256, DSM64>>>(
        (float*)p_h1, nullptr, HID, 64, (const float*)p_s1, HID, 64, 1, 0, 3,
        (bf*)p_m1hi, (bf*)p_m1lo, HEADS * EMB, EMB, (bf*)p_Wv1hi, (bf*)p_Wv1lo, EMB, 64 * EMB, EMB);
    // 8: [s2 | q2] = A2 @ [Ws2;Wq2]^T (3-pass, split epilogue)
    mma_gemm<128><<<dim3(8, 8, 1), 256, DSM128>>>(
        (float*)p_s2, (bf*)p_q2hi, HID, 0, nullptr, 0, 0, 3, HID, 3,
        (bf*)p_A2hi, (bf*)p_A2lo, EMB, 0, (bf*)p_B2chi, (bf*)p_B2clo, EMB, 0, EMB);
    // 9: u2 = q2_h @ Wk2t_h^T (1-pass, bf16), K=64
    mma_gemm<128><<<dim3(4, 8, 8), 256, DSM128>>>(
        nullptr, (bf*)p_u2, HEADS * HID, HID, nullptr, 0, 0, 2, 0, 1,
        (bf*)p_q2hi, (bf*)p_q2hi, HID, 64, (bf*)p_Wk2thi, nullptr, 64, HID * 64, 64);
    // 10: attention layer 2
    attn2_kernel<<<NB_B, 256>>>();
    // 11: out = relu(s2 + m2_h @ Wv2_h^T) (3-pass), K=512, N=64 per head
    mma_gemm<64><<<dim3(1, 8, 8), 256, DSM64>>>(
        out, nullptr, HID, 64, (const float*)p_s2, HID, 64, 1, 0, 3,
        (bf*)p_m2hi, (bf*)p_m2lo, HEADS * HID, HID, (bf*)p_Wv2hi, (bf*)p_Wv2lo, HID, 64 * HID, HID);
}

// round 14
// speedup vs baseline: 1.0841x; 1.0079x over previous
#include <cuda_runtime.h>
#include <cuda_bf16.h>
#include <cstdint>

#define NB_B 1024
#define FAN_1 15
#define FAN_2 10
#define EMB 256
#define HID 512
#define HEADS 8
#define N1 (NB_B * FAN_1)
#define N2 (N1 * FAN_2)
#define W4 (HID * EMB / 4)

typedef __nv_bfloat16 bf;

// ---------------- scratch (16B-aligned for cp.async) ----------------
__device__ int g_seeds[NB_B];
__device__ int g_nbr1[N1];
__device__ int g_nbr2[N2];
__device__ __align__(16) bf g_Bs1hi[HID * EMB], g_Bs1lo[HID * EMB];
__device__ __align__(16) bf g_Bq1hi[HID * EMB], g_Bq1lo[HID * EMB];
__device__ __align__(16) bf g_B2chi[2 * HID * EMB], g_B2clo[2 * HID * EMB];  // [Ws2;Wq2]
__device__ __align__(16) bf g_Wv1hi[HID * EMB], g_Wv1lo[HID * EMB];
__device__ __align__(16) bf g_Wv2hi[HID * HID], g_Wv2lo[HID * HID];
__device__ __align__(16) bf g_Wk1thi[HEADS * EMB * 64], g_Wk1tlo[HEADS * EMB * 64];
__device__ __align__(16) bf g_Wk2thi[HEADS * HID * 64], g_Wk2tlo[HEADS * HID * 64];
__device__ __align__(16) bf g_A1hi[(size_t)N1 * EMB], g_A1lo[(size_t)N1 * EMB];
__device__ __align__(16) bf g_A2hi[(size_t)NB_B * EMB], g_A2lo[(size_t)NB_B * EMB];
__device__ __align__(16) float g_s1[(size_t)N1 * HID];
__device__ __align__(16) bf g_q1hi[(size_t)N1 * HID];
__device__ __align__(16) bf g_u1[(size_t)N1 * HEADS * EMB];
__device__ __align__(16) bf g_m1hi[(size_t)N1 * HEADS * EMB], g_m1lo[(size_t)N1 * HEADS * EMB];
__device__ __align__(16) float g_h1[(size_t)N1 * HID];
__device__ __align__(16) float g_s2[(size_t)NB_B * HID];
__device__ __align__(16) bf g_q2hi[(size_t)NB_B * HID];
__device__ __align__(16) bf g_u2[(size_t)NB_B * HEADS * HID];
__device__ __align__(16) bf g_m2hi[(size_t)NB_B * HEADS * HID], g_m2lo[(size_t)NB_B * HEADS * HID];

// ---------------- helpers ----------------
__device__ __forceinline__ uint32_t smem_u32(const void* p) {
    uint32_t a;
    asm("{ .reg .u64 t; cvta.to.shared.u64 t, %1; cvt.u32.u64 %0, t; }" : "=r"(a) : "l"(p));
    return a;
}
__device__ __forceinline__ void cp16(uint32_t s, const void* g) {
    asm volatile("cp.async.cg.shared.global [%0], [%1], 16;" :: "r"(s), "l"(g));
}
__device__ __forceinline__ void cp_commit() { asm volatile("cp.async.commit_group;" ::: "memory"); }
__device__ __forceinline__ void cp_wait1() { asm volatile("cp.async.wait_group 1;" ::: "memory"); }
__device__ __forceinline__ void ldmA(uint32_t* a, uint32_t addr) {
    asm volatile("ldmatrix.sync.aligned.m8n8.x4.shared.b16 {%0,%1,%2,%3}, [%4];"
                 : "=r"(a[0]), "=r"(a[1]), "=r"(a[2]), "=r"(a[3]) : "r"(addr));
}
__device__ __forceinline__ void ldmB4(uint32_t* b, uint32_t addr) {
    asm volatile("ldmatrix.sync.aligned.m8n8.x4.shared.b16 {%0,%1,%2,%3}, [%4];"
                 : "=r"(b[0]), "=r"(b[1]), "=r"(b[2]), "=r"(b[3]) : "r"(addr));
}
__device__ __forceinline__ void mma16816(float* d, const uint32_t* a, const uint32_t* b) {
    asm volatile("mma.sync.aligned.m16n8k16.row.col.f32.bf16.bf16.f32 "
                 "{%0,%1,%2,%3}, {%4,%5,%6,%7}, {%8,%9}, {%0,%1,%2,%3};"
                 : "+f"(d[0]), "+f"(d[1]), "+f"(d[2]), "+f"(d[3])
                 : "r"(a[0]), "r"(a[1]), "r"(a[2]), "r"(a[3]), "r"(b[0]), "r"(b[1]));
}

// ---------------- index conversion ----------------
__global__ void convert_idx(const void* sv, const void* n1v, const void* n2v) {
    const unsigned long long* p = (const unsigned long long*)sv;
    bool is64 = (((p[0] | p[1] | p[2] | p[3]) >> 32) == 0ULL);
    int t = blockIdx.x * blockDim.x + threadIdx.x;
    int stride = gridDim.x * blockDim.x;
    if (is64) {
        const long long* a = (const long long*)sv;
        const long long* b = (const long long*)n1v;
        const long long* c = (const long long*)n2v;
        if (t < NB_B) g_seeds[t] = (int)a[t];
        if (t < N1)   g_nbr1[t]  = (int)b[t];
        for (int i = t; i < N2; i += stride) g_nbr2[i] = (int)c[i];
    } else {
        const int* a = (const int*)sv;
        const int* b = (const int*)n1v;
        const int* c = (const int*)n2v;
        if (t < NB_B) g_seeds[t] = a[t];
        if (t < N1)   g_nbr1[t]  = b[t];
        for (int i = t; i < N2; i += stride) g_nbr2[i] = c[i];
    }
}

// ---------------- splits ----------------
__device__ __forceinline__ void split4(float4 x, __nv_bfloat162* hp, __nv_bfloat162* lp) {
    bf h0 = __float2bfloat16(x.x), h1 = __float2bfloat16(x.y);
    bf h2 = __float2bfloat16(x.z), h3 = __float2bfloat16(x.w);
    __nv_bfloat162 H0; H0.x = h0; H0.y = h1;
    __nv_bfloat162 H1; H1.x = h2; H1.y = h3;
    __nv_bfloat162 L0, L1;
    L0.x = __float2bfloat16(x.x - __bfloat162float(h0));
    L0.y = __float2bfloat16(x.y - __bfloat162float(h1));
    L1.x = __float2bfloat16(x.z - __bfloat162float(h2));
    L1.y = __float2bfloat16(x.w - __bfloat162float(h3));
    hp[0] = H0; hp[1] = H1; lp[0] = L0; lp[1] = L1;
}

// all weight preps in ONE kernel. y: 0..5 = wsplit jobs, 6/7 = tsplit Wk1/Wk2.
__global__ void prep_all(const float* __restrict__ Ws1, const float* __restrict__ Wq1,
                         const float* __restrict__ Ws2, const float* __restrict__ Wq2,
                         const float* __restrict__ Wv1, const float* __restrict__ Wv2,
                         const float* __restrict__ Wk1, const float* __restrict__ Wk2) {
    int y = blockIdx.y, bx = blockIdx.x, tid = threadIdx.x;
    if (y < 6) {
        const float* src; bf *hi, *lo; int n4;
        switch (y) {
            case 0: src = Ws1; hi = g_Bs1hi; lo = g_Bs1lo; n4 = W4; break;
            case 1: src = Wq1; hi = g_Bq1hi; lo = g_Bq1lo; n4 = W4; break;
            case 2: src = Ws2; hi = g_B2chi; lo = g_B2clo; n4 = W4; break;
            case 3: src = Wq2; hi = g_B2chi + (size_t)HID * EMB; lo = g_B2clo + (size_t)HID * EMB; n4 = W4; break;
            case 4: src = Wv1; hi = g_Wv1hi; lo = g_Wv1lo; n4 = W4; break;
            default: src = Wv2; hi = g_Wv2hi; lo = g_Wv2lo; n4 = 2 * W4; break;
        }
        int i = bx * 256 + tid;
        if (i < n4)
            split4(((const float4*)src)[i], (__nv_bfloat162*)hi + 2 * i, (__nv_bfloat162*)lo + 2 * i);
    } else {
        __shared__ float tile[64][33];
        const float* src = (y == 6) ? Wk1 : Wk2;
        bf* hi = (y == 6) ? g_Wk1thi : g_Wk2thi;
        bf* lo = (y == 6) ? g_Wk1tlo : g_Wk2tlo;
        int Ecols = (y == 6) ? EMB : HID;
        int ntiles = HEADS * (Ecols / 32);
        if (bx >= ntiles) return;
        int h = bx / (Ecols / 32), e0 = (bx % (Ecols / 32)) * 32;
        int tx = tid & 31, ty = tid >> 5;  // 32 x 8
#pragma unroll
        for (int j = 0; j < 8; j++) {
            int d = ty + 8 * j;
            tile[d][tx] = src[(size_t)(h * 64 + d) * Ecols + e0 + tx];
        }
        __syncthreads();
#pragma unroll
        for (int j = 0; j < 4; j++) {
            int e = ty + 8 * j;
            size_t o = (size_t)(h * Ecols + e0 + e) * 64;
            float x0 = tile[tx][e], x1 = tile[tx + 32][e];
            bf h0 = __float2bfloat16(x0), h1 = __float2bfloat16(x1);
            hi[o + tx] = h0; hi[o + tx + 32] = h1;
            lo[o + tx] = __float2bfloat16(x0 - __bfloat162float(h0));
            lo[o + tx + 32] = __float2bfloat16(x1 - __bfloat162float(h1));
        }
    }
}

// both embedding gathers in one kernel. y=0: A1 via nbr1 (N1 rows), y=1: A2 via seeds.
__global__ void gsplit_all(const float* __restrict__ emb) {
    int y = blockIdx.y;
    int i = blockIdx.x * 256 + threadIdx.x;
    if (y == 0) {
        if (i < N1 * 64) {
            int r = i >> 6, c = i & 63;
            float4 x = ((const float4*)(emb + (size_t)g_nbr1[r] * EMB))[c];
            split4(x, (__nv_bfloat162*)g_A1hi + 2 * i, (__nv_bfloat162*)g_A1lo + 2 * i);
        }
    } else {
        if (i < NB_B * 64) {
            int r = i >> 6, c = i & 63;
            float4 x = ((const float4*)(emb + (size_t)g_seeds[r] * EMB))[c];
            split4(x, (__nv_bfloat162*)g_A2hi + 2 * i, (__nv_bfloat162*)g_A2lo + 2 * i);
        }
    }
}

// ---------------- 3-stage cp.async mma GEMM: C = A @ B^T, block 128 x BN ----------------
// K-chunk 64 (128B rows), XOR swizzle, warp tile 32 x (BN/2). ONE sync per chunk:
// at iter i, issue(i+2) writes buf (i+2)%3 == (i-1)%3, whose readers all passed this
// iteration's barrier. One commit per iter => wait_group(1) retires group i.
// npass: 3 = hi/lo cross-terms, 1 = hi only.
// modes: 0 fp32 C; 1 relu(acc+E) fp32; 2 bf16 Chi; 3 col<nsplit ? fp32 C : bf16 Chi (col-nsplit).
template <int BN>
__global__ __launch_bounds__(256, 2) void mma_gemm(
    float* __restrict__ C, bf* __restrict__ Chi, int ldc, int coffz,
    const float* __restrict__ E, int lde, int eoffz, int mode, int nsplit, int npass,
    const bf* __restrict__ Ahi, const bf* __restrict__ Alo, int lda, int aoffz,
    const bf* __restrict__ Bhi, const bf* __restrict__ Blo, int ldb, int bz,
    int K)
{
    extern __shared__ __align__(16) char dynsm[];
    constexpr int NI = BN / 16;       // n-frags per warp (8 or 4)
    constexpr int NP = BN / 32;       // ldmB4 per s-step / B load iters
    constexpr uint32_t BSTRIDE = BN * 128;
    const uint32_t asb = smem_u32(dynsm);            // 3 x 16KB A
    const uint32_t bsb = asb + 3 * 16384u;           // 3 x BN*128 B
    const int tid = threadIdx.x, lane = tid & 31, wid = tid >> 5;
    const int z = blockIdx.z, m0 = blockIdx.y * 128, n0 = blockIdx.x * BN;
    const int wm = wid & 3, wn = wid >> 2;           // 4(m) x 2(n)
    const int aoff = z * aoffz;
    const bf* Bh = Bhi + (size_t)z * bz;
    const bf* Bl = Blo ? (Blo + (size_t)z * bz) : Bh;
    const int kc = K >> 6, nch = npass * kc;

    const int lr = tid >> 3;
    const int lch = tid & 7;
    const uint32_t lsw = (uint32_t)((lch ^ (lr & 7)) * 16);

    auto issue = [&](int c) {
        int pass = c / kc, k0 = (c - pass * kc) << 6;
        const bf* Ap = (pass == 2) ? Alo : Ahi;
        const bf* Bp = (pass == 1) ? Bl : Bh;
        int buf = c % 3;
        uint32_t sa = asb + buf * 16384u, sb = bsb + buf * BSTRIDE;
#pragma unroll
        for (int i = 0; i < 4; i++) {
            int rr = lr + 32 * i;
            cp16(sa + rr * 128 + lsw, Ap + (size_t)(m0 + rr) * lda + aoff + k0 + lch * 8);
        }
#pragma unroll
        for (int i = 0; i < NP; i++) {
            int rr = lr + 32 * i;
            cp16(sb + rr * 128 + lsw, Bp + (size_t)(n0 + rr) * ldb + k0 + lch * 8);
        }
        cp_commit();
    };

    float acc[2][NI][4];
#pragma unroll
    for (int i = 0; i < 2; i++)
#pragma unroll
        for (int j = 0; j < NI; j++)
#pragma unroll
            for (int k = 0; k < 4; k++) acc[i][j][k] = 0.f;

    issue(0);
    if (nch > 1) issue(1); else cp_commit();

    for (int i = 0; i < nch; i++) {
        cp_wait1();
        __syncthreads();
        if (i + 2 < nch) issue(i + 2); else cp_commit();
        uint32_t ab = asb + (i % 3) * 16384u;
        uint32_t bb = bsb + (i % 3) * BSTRIDE;
#pragma unroll
        for (int s = 0; s < 4; s++) {
            uint32_t bq[NP][4];
#pragma unroll
            for (int np = 0; np < NP; np++) {
                int g = lane >> 3;
                int brow = wn * (BN / 2) + np * 16 + (g >> 1) * 8 + (lane & 7);
                int bch = s * 2 + (g & 1);
                ldmB4(bq[np], bb + brow * 128 + ((bch ^ (brow & 7)) * 16));
            }
#pragma unroll
            for (int mi = 0; mi < 2; mi++) {
                int arow = wm * 32 + mi * 16 + (lane & 15);
                int ach = s * 2 + (lane >> 4);
                uint32_t afr[4];
                ldmA(afr, ab + arow * 128 + ((ach ^ (arow & 7)) * 16));
#pragma unroll
                for (int ni = 0; ni < NI; ni++)
                    mma16816(acc[mi][ni], afr, &bq[ni >> 1][(ni & 1) * 2]);
            }
        }
    }

    const int r0 = lane >> 2, cp = (lane & 3) * 2;
#pragma unroll
    for (int mi = 0; mi < 2; mi++) {
#pragma unroll
        for (int half = 0; half < 2; half++) {
            int row = m0 + wm * 32 + mi * 16 + r0 + half * 8;
#pragma unroll
            for (int ni = 0; ni < NI; ni++) {
                int col = n0 + wn * (BN / 2) + ni * 8 + cp;
                float v0 = acc[mi][ni][half * 2 + 0];
                float v1 = acc[mi][ni][half * 2 + 1];
                bool qside = (mode == 2) || (mode == 3 && col >= nsplit);
                if (mode == 1) {
                    size_t off = (size_t)row * ldc + z * coffz + col;
                    size_t eo = (size_t)row * lde + z * eoffz + col;
                    float2 ev = *(const float2*)(E + eo);
                    float2 o;
                    o.x = fmaxf(v0 + ev.x, 0.f);
                    o.y = fmaxf(v1 + ev.y, 0.f);
                    *(float2*)(C + off) = o;
                } else if (qside) {
                    size_t off = (size_t)row * ldc + z * coffz + (col - nsplit);
                    __nv_bfloat162 hh;
                    hh.x = __float2bfloat16(v0);
                    hh.y = __float2bfloat16(v1);
                    *(__nv_bfloat162*)(Chi + off) = hh;
                } else {
                    size_t off = (size_t)row * ldc + z * coffz + col;
                    float2 o; o.x = v0; o.y = v1;
                    *(float2*)(C + off) = o;
                }
            }
        }
    }
}

// ---------------- fused attention layer 1 (u in bf16) ----------------
__global__ __launch_bounds__(256) void attn1_kernel(const float* __restrict__ emb) {
    __shared__ float sh2[FAN_2][EMB];
    int n = blockIdx.x, tid = threadIdx.x;
    for (int i = tid; i < FAN_2 * 64; i += 256) {
        int f = i >> 6, c = i & 63;
        ((float4*)sh2[f])[c] = ((const float4*)(emb + (size_t)g_nbr2[n * FAN_2 + f] * EMB))[c];
    }
    int w = tid >> 5, l = tid & 31;
    const bf* up = g_u1 + (size_t)n * (HEADS * EMB) + w * EMB;
    float u[8];
#pragma unroll
    for (int j = 0; j < 8; j++) u[j] = __bfloat162float(up[l + j * 32]);
    __syncthreads();

    float at[FAN_2], mx = -1e30f;
#pragma unroll
    for (int f = 0; f < FAN_2; f++) {
        float p = 0.f;
#pragma unroll
        for (int j = 0; j < 8; j++) p += sh2[f][l + j * 32] * u[j];
#pragma unroll
        for (int o = 16; o; o >>= 1) p += __shfl_xor_sync(0xffffffffu, p, o);
        p *= 0.125f;
        at[f] = p; mx = fmaxf(mx, p);
    }
    float s = 0.f;
#pragma unroll
    for (int f = 0; f < FAN_2; f++) { at[f] = expf(at[f] - mx); s += at[f]; }
    float inv = 1.f / s;
    size_t mo = (size_t)n * (HEADS * EMB) + w * EMB;
#pragma unroll
    for (int j = 0; j < 8; j++) {
        int e = l + j * 32;
        float m = 0.f;
#pragma unroll
        for (int f = 0; f < FAN_2; f++) m += at[f] * sh2[f][e];
        m *= inv;
        bf h = __float2bfloat16(m);
        g_m1hi[mo + e] = h;
        g_m1lo[mo + e] = __float2bfloat16(m - __bfloat162float(h));
    }
}

// ---------------- fused attention layer 2 (u in bf16) ----------------
__global__ __launch_bounds__(256) void attn2_kernel() {
    __shared__ float sh1[FAN_1][HID];
    int b = blockIdx.x, tid = threadIdx.x;
    const float4* hp = (const float4*)(g_h1 + (size_t)b * FAN_1 * HID);
    for (int i = tid; i < FAN_1 * HID / 4; i += 256) ((float4*)&sh1[0][0])[i] = hp[i];
    int w = tid >> 5, l = tid & 31;
    const bf* up = g_u2 + (size_t)b * (HEADS * HID) + w * HID;
    float u[16];
#pragma unroll
    for (int j = 0; j < 16; j++) u[j] = __bfloat162float(up[l + j * 32]);
    __syncthreads();

    float at[FAN_1], mx = -1e30f;
#pragma unroll
    for (int f = 0; f < FAN_1; f++) {
        float p = 0.f;
#pragma unroll
        for (int j = 0; j < 16; j++) p += sh1[f][l + j * 32] * u[j];
#pragma unroll
        for (int o = 16; o; o >>= 1) p += __shfl_xor_sync(0xffffffffu, p, o);
        p *= 0.125f;
        at[f] = p; mx = fmaxf(mx, p);
    }
    float s = 0.f;
#pragma unroll
    for (int f = 0; f < FAN_1; f++) { at[f] = expf(at[f] - mx); s += at[f]; }
    float inv = 1.f / s;
    size_t mo = (size_t)b * (HEADS * HID) + w * HID;
#pragma unroll
    for (int j = 0; j < 16; j++) {
        int e = l + j * 32;
        float m = 0.f;
#pragma unroll
        for (int f = 0; f < FAN_1; f++) m += at[f] * sh1[f][e];
        m *= inv;
        bf h = __float2bfloat16(m);
        g_m2hi[mo + e] = h;
        g_m2lo[mo + e] = __float2bfloat16(m - __bfloat162float(h));
    }
}

// ---------------- host ----------------
#define GET(n) void* p_##n; cudaGetSymbolAddress(&p_##n, g_##n)
#define DSM128 (3 * 16384 + 3 * 128 * 128)   /* 98304 */
#define DSM64  (3 * 16384 + 3 * 64 * 128)    /* 73728 */

extern "C" void kernel_launch(void* const* d_in, const int* in_sizes, int n_in,
                              void* d_out, int out_size) {
    const void* seeds = d_in[0];
    const void* nbr1  = d_in[1];
    const void* nbr2  = d_in[2];
    const float* emb = (const float*)d_in[3];
    const float* Wq1 = (const float*)d_in[4];
    const float* Wk1 = (const float*)d_in[5];
    const float* Wv1 = (const float*)d_in[6];
    const float* Ws1 = (const float*)d_in[7];
    const float* Wq2 = (const float*)d_in[8];
    const float* Wk2 = (const float*)d_in[9];
    const float* Wv2 = (const float*)d_in[10];
    const float* Ws2 = (const float*)d_in[11];
    float* out = (float*)d_out;

    GET(Bs1hi); GET(Bs1lo); GET(Bq1hi); GET(Bq1lo);
    GET(B2chi); GET(B2clo);
    GET(Wv1hi); GET(Wv1lo); GET(Wv2hi); GET(Wv2lo);
    GET(Wk1thi); GET(Wk1tlo); GET(Wk2thi); GET(Wk2tlo);
    GET(A1hi); GET(A1lo); GET(A2hi); GET(A2lo);
    GET(s1); GET(q1hi); GET(u1); GET(m1hi); GET(m1lo); GET(h1);
    GET(s2); GET(q2hi); GET(u2); GET(m2hi); GET(m2lo);

    cudaFuncSetAttribute(mma_gemm<128>, cudaFuncAttributeMaxDynamicSharedMemorySize, DSM128);
    cudaFuncSetAttribute(mma_gemm<64>,  cudaFuncAttributeMaxDynamicSharedMemorySize, DSM64);

    // 0: indices
    convert_idx<<<600, 256>>>(seeds, nbr1, nbr2);
    // 1: all weight splits + transposes
    prep_all<<<dim3(256, 8), 256>>>(Ws1, Wq1, Ws2, Wq2, Wv1, Wv2, Wk1, Wk2);
    // 2: both embedding gathers
    gsplit_all<<<dim3(N1 * 64 / 256, 2), 256>>>(emb);
    // 3: s1 = A1 @ Ws1^T (3-pass fp32)  <-- profiled launch
    mma_gemm<128><<<dim3(4, 120, 1), 256, DSM128>>>(
        (float*)p_s1, nullptr, HID, 0, nullptr, 0, 0, 0, 0, 3,
        (bf*)p_A1hi, (bf*)p_A1lo, EMB, 0, (bf*)p_Bs1hi, (bf*)p_Bs1lo, EMB, 0, EMB);
    // 4: q1 = A1 @ Wq1^T (1-pass, bf16)
    mma_gemm<128><<<dim3(4, 120, 1), 256, DSM128>>>(
        nullptr, (bf*)p_q1hi, HID, 0, nullptr, 0, 0, 2, 0, 1,
        (bf*)p_A1hi, (bf*)p_A1hi, EMB, 0, (bf*)p_Bq1hi, nullptr, EMB, 0, EMB);
    // 5: u1 = q1_h @ Wk1t_h^T (1-pass, bf16), K=64
    mma_gemm<128><<<dim3(2, 120, 8), 256, DSM128>>>(
        nullptr, (bf*)p_u1, HEADS * EMB, EMB, nullptr, 0, 0, 2, 0, 1,
        (bf*)p_q1hi, (bf*)p_q1hi, HID, 64, (bf*)p_Wk1thi, nullptr, 64, EMB * 64, 64);
    // 6: attention layer 1
    attn1_kernel<<<N1, 256>>>(emb);
    // 7: h1 = relu(s1 + m1_h @ Wv1_h^T) (3-pass), N=64 per head
    mma_gemm<64><<<dim3(1, 120, 8), 256, DSM64>>>(
        (float*)p_h1, nullptr, HID, 64, (const float*)p_s1, HID, 64, 1, 0, 3,
        (bf*)p_m1hi, (bf*)p_m1lo, HEADS * EMB, EMB, (bf*)p_Wv1hi, (bf*)p_Wv1lo, EMB, 64 * EMB, EMB);
    // 8: [s2 | q2] = A2 @ [Ws2;Wq2]^T (3-pass, split epilogue)
    mma_gemm<128><<<dim3(8, 8, 1), 256, DSM128>>>(
        (float*)p_s2, (bf*)p_q2hi, HID, 0, nullptr, 0, 0, 3, HID, 3,
        (bf*)p_A2hi, (bf*)p_A2lo, EMB, 0, (bf*)p_B2chi, (bf*)p_B2clo, EMB, 0, EMB);
    // 9: u2 = q2_h @ Wk2t_h^T (1-pass, bf16), K=64
    mma_gemm<128><<<dim3(4, 8, 8), 256, DSM128>>>(
        nullptr, (bf*)p_u2, HEADS * HID, HID, nullptr, 0, 0, 2, 0, 1,
        (bf*)p_q2hi, (bf*)p_q2hi, HID, 64, (bf*)p_Wk2thi, nullptr, 64, HID * 64, 64);
    // 10: attention layer 2
    attn2_kernel<<<NB_B, 256>>>();
    // 11: out = relu(s2 + m2_h @ Wv2_h^T) (3-pass), K=512, N=64 per head
    mma_gemm<64><<<dim3(1, 8, 8), 256, DSM64>>>(
        out, nullptr, HID, 64, (const float*)p_s2, HID, 64, 1, 0, 3,
        (bf*)p_m2hi, (bf*)p_m2lo, HEADS * HID, HID, (bf*)p_Wv2hi, (bf*)p_Wv2lo, HID, 64 * HID, HID);
}

// round 15
// speedup vs baseline: 1.2443x; 1.1478x over previous
#include <cuda_runtime.h>
#include <cuda_bf16.h>
#include <cstdint>

#define NB_B 1024
#define FAN_1 15
#define FAN_2 10
#define EMB 256
#define HID 512
#define HEADS 8
#define N1 (NB_B * FAN_1)
#define N2 (N1 * FAN_2)
#define W4 (HID * EMB / 4)

typedef __nv_bfloat16 bf;

// ---------------- scratch (16B-aligned for cp.async) ----------------
__device__ int g_nbr2[N2];
__device__ __align__(16) bf g_Bs1hi[HID * EMB], g_Bs1lo[HID * EMB];
__device__ __align__(16) bf g_Bq1hi[HID * EMB], g_Bq1lo[HID * EMB];
__device__ __align__(16) bf g_B2chi[2 * HID * EMB], g_B2clo[2 * HID * EMB];  // [Ws2;Wq2]
__device__ __align__(16) bf g_Wv1hi[HID * EMB], g_Wv1lo[HID * EMB];
__device__ __align__(16) bf g_Wv2hi[HID * HID], g_Wv2lo[HID * HID];
__device__ __align__(16) bf g_Wk1thi[HEADS * EMB * 64], g_Wk1tlo[HEADS * EMB * 64];
__device__ __align__(16) bf g_Wk2thi[HEADS * HID * 64], g_Wk2tlo[HEADS * HID * 64];
__device__ __align__(16) bf g_A1hi[(size_t)N1 * EMB], g_A1lo[(size_t)N1 * EMB];
__device__ __align__(16) bf g_A2hi[(size_t)NB_B * EMB], g_A2lo[(size_t)NB_B * EMB];
__device__ __align__(16) float g_s1[(size_t)N1 * HID];
__device__ __align__(16) bf g_q1hi[(size_t)N1 * HID];
__device__ __align__(16) bf g_u1[(size_t)N1 * HEADS * EMB];
__device__ __align__(16) bf g_m1hi[(size_t)N1 * HEADS * EMB], g_m1lo[(size_t)N1 * HEADS * EMB];
__device__ __align__(16) float g_h1[(size_t)N1 * HID];
__device__ __align__(16) float g_s2[(size_t)NB_B * HID];
__device__ __align__(16) bf g_q2hi[(size_t)NB_B * HID];
__device__ __align__(16) bf g_u2[(size_t)NB_B * HEADS * HID];
__device__ __align__(16) bf g_m2hi[(size_t)NB_B * HEADS * HID], g_m2lo[(size_t)NB_B * HEADS * HID];

// ---------------- helpers ----------------
__device__ __forceinline__ uint32_t smem_u32(const void* p) {
    uint32_t a;
    asm("{ .reg .u64 t; cvta.to.shared.u64 t, %1; cvt.u32.u64 %0, t; }" : "=r"(a) : "l"(p));
    return a;
}
__device__ __forceinline__ void cp16(uint32_t s, const void* g) {
    asm volatile("cp.async.cg.shared.global [%0], [%1], 16;" :: "r"(s), "l"(g));
}
__device__ __forceinline__ void cp_commit() { asm volatile("cp.async.commit_group;" ::: "memory"); }
__device__ __forceinline__ void cp_wait1() { asm volatile("cp.async.wait_group 1;" ::: "memory"); }
__device__ __forceinline__ void cp_wait0() { asm volatile("cp.async.wait_group 0;" ::: "memory"); }
__device__ __forceinline__ void ldmA(uint32_t* a, uint32_t addr) {
    asm volatile("ldmatrix.sync.aligned.m8n8.x4.shared.b16 {%0,%1,%2,%3}, [%4];"
                 : "=r"(a[0]), "=r"(a[1]), "=r"(a[2]), "=r"(a[3]) : "r"(addr));
}
__device__ __forceinline__ void ldmB4(uint32_t* b, uint32_t addr) {
    asm volatile("ldmatrix.sync.aligned.m8n8.x4.shared.b16 {%0,%1,%2,%3}, [%4];"
                 : "=r"(b[0]), "=r"(b[1]), "=r"(b[2]), "=r"(b[3]) : "r"(addr));
}
__device__ __forceinline__ void mma16816(float* d, const uint32_t* a, const uint32_t* b) {
    asm volatile("mma.sync.aligned.m16n8k16.row.col.f32.bf16.bf16.f32 "
                 "{%0,%1,%2,%3}, {%4,%5,%6,%7}, {%8,%9}, {%0,%1,%2,%3};"
                 : "+f"(d[0]), "+f"(d[1]), "+f"(d[2]), "+f"(d[3])
                 : "r"(a[0]), "r"(a[1]), "r"(a[2]), "r"(a[3]), "r"(b[0]), "r"(b[1]));
}

// raw index decode (int64 vs int32 dump)
__device__ __forceinline__ bool det64(const void* p) {
    const unsigned long long* q = (const unsigned long long*)p;
    return (((q[0] | q[1] | q[2] | q[3]) >> 32) == 0ULL);
}
__device__ __forceinline__ int rd_idx(const void* p, int r, bool is64) {
    return is64 ? (int)((const long long*)p)[r] : ((const int*)p)[r];
}

// ---------------- splits ----------------
__device__ __forceinline__ void split4(float4 x, __nv_bfloat162* hp, __nv_bfloat162* lp) {
    bf h0 = __float2bfloat16(x.x), h1 = __float2bfloat16(x.y);
    bf h2 = __float2bfloat16(x.z), h3 = __float2bfloat16(x.w);
    __nv_bfloat162 H0; H0.x = h0; H0.y = h1;
    __nv_bfloat162 H1; H1.x = h2; H1.y = h3;
    __nv_bfloat162 L0, L1;
    L0.x = __float2bfloat16(x.x - __bfloat162float(h0));
    L0.y = __float2bfloat16(x.y - __bfloat162float(h1));
    L1.x = __float2bfloat16(x.z - __bfloat162float(h2));
    L1.y = __float2bfloat16(x.w - __bfloat162float(h3));
    hp[0] = H0; hp[1] = H1; lp[0] = L0; lp[1] = L1;
}

// ---------------- ONE mega-prep kernel (segment-dispatched 1D grid) ----------------
// segs: [0,640) wsplits Ws1/Wq1/Ws2/Wq2/Wv1 (128 blocks each)
//       [640,896) Wv2 split (256)
//       [896,960) tsplit Wk1 (64)   [960,1088) tsplit Wk2 (128)
//       [1088,1688) nbr2 convert (600)
//       [1688,5528) A1 gather (3840)   [5528,5784) A2 gather (256)
#define PREP_BLOCKS 5784
__global__ __launch_bounds__(256) void prep_mega(
    const float* __restrict__ Ws1, const float* __restrict__ Wq1,
    const float* __restrict__ Ws2, const float* __restrict__ Wq2,
    const float* __restrict__ Wv1, const float* __restrict__ Wv2,
    const float* __restrict__ Wk1, const float* __restrict__ Wk2,
    const void* seeds, const void* nbr1, const void* nbr2,
    const float* __restrict__ emb)
{
    int b = blockIdx.x, tid = threadIdx.x;
    if (b < 640) {
        int y = b >> 7, bx = b & 127;
        const float* src; bf *hi, *lo;
        switch (y) {
            case 0: src = Ws1; hi = g_Bs1hi; lo = g_Bs1lo; break;
            case 1: src = Wq1; hi = g_Bq1hi; lo = g_Bq1lo; break;
            case 2: src = Ws2; hi = g_B2chi; lo = g_B2clo; break;
            case 3: src = Wq2; hi = g_B2chi + (size_t)HID * EMB; lo = g_B2clo + (size_t)HID * EMB; break;
            default: src = Wv1; hi = g_Wv1hi; lo = g_Wv1lo; break;
        }
        int i = bx * 256 + tid;
        split4(((const float4*)src)[i], (__nv_bfloat162*)hi + 2 * i, (__nv_bfloat162*)lo + 2 * i);
    } else if (b < 896) {
        int i = (b - 640) * 256 + tid;
        split4(((const float4*)Wv2)[i], (__nv_bfloat162*)g_Wv2hi + 2 * i, (__nv_bfloat162*)g_Wv2lo + 2 * i);
    } else if (b < 1088) {
        bool k1 = (b < 960);
        int bx = k1 ? (b - 896) : (b - 960);
        __shared__ float tile[64][33];
        const float* src = k1 ? Wk1 : Wk2;
        bf* hi = k1 ? g_Wk1thi : g_Wk2thi;
        bf* lo = k1 ? g_Wk1tlo : g_Wk2tlo;
        int Ecols = k1 ? EMB : HID;
        int h = bx / (Ecols / 32), e0 = (bx % (Ecols / 32)) * 32;
        int tx = tid & 31, ty = tid >> 5;
#pragma unroll
        for (int j = 0; j < 8; j++) {
            int d = ty + 8 * j;
            tile[d][tx] = src[(size_t)(h * 64 + d) * Ecols + e0 + tx];
        }
        __syncthreads();
#pragma unroll
        for (int j = 0; j < 4; j++) {
            int e = ty + 8 * j;
            size_t o = (size_t)(h * Ecols + e0 + e) * 64;
            float x0 = tile[tx][e], x1 = tile[tx + 32][e];
            bf h0 = __float2bfloat16(x0), h1 = __float2bfloat16(x1);
            hi[o + tx] = h0; hi[o + tx + 32] = h1;
            lo[o + tx] = __float2bfloat16(x0 - __bfloat162float(h0));
            lo[o + tx + 32] = __float2bfloat16(x1 - __bfloat162float(h1));
        }
    } else if (b < 1688) {
        bool is64 = det64(nbr2);
        int t = (b - 1088) * 256 + tid;
        for (int i = t; i < N2; i += 600 * 256) g_nbr2[i] = rd_idx(nbr2, i, is64);
    } else if (b < 5528) {
        bool is64 = det64(nbr1);
        int i = (b - 1688) * 256 + tid;     // < N1*64
        int r = i >> 6, c = i & 63;
        float4 x = ((const float4*)(emb + (size_t)rd_idx(nbr1, r, is64) * EMB))[c];
        split4(x, (__nv_bfloat162*)g_A1hi + 2 * i, (__nv_bfloat162*)g_A1lo + 2 * i);
    } else {
        bool is64 = det64(seeds);
        int i = (b - 5528) * 256 + tid;     // < NB_B*64
        int r = i >> 6, c = i & 63;
        float4 x = ((const float4*)(emb + (size_t)rd_idx(seeds, r, is64) * EMB))[c];
        split4(x, (__nv_bfloat162*)g_A2hi + 2 * i, (__nv_bfloat162*)g_A2lo + 2 * i);
    }
}

// ---------------- 3-stage cp.async mma GEMM: C = A @ B^T, block 128 x BN ----------------
// npass: 3 = hi/lo cross-terms, 1 = hi only.
// modes: 0 fp32 C; 1 relu(acc+E) fp32; 2 bf16 Chi; 3 col<nsplit ? fp32 C : bf16 Chi (col-nsplit).
template <int BN>
__global__ __launch_bounds__(256, 2) void mma_gemm(
    float* __restrict__ C, bf* __restrict__ Chi, int ldc, int coffz,
    const float* __restrict__ E, int lde, int eoffz, int mode, int nsplit, int npass,
    const bf* __restrict__ Ahi, const bf* __restrict__ Alo, int lda, int aoffz,
    const bf* __restrict__ Bhi, const bf* __restrict__ Blo, int ldb, int bz,
    int K)
{
    extern __shared__ __align__(16) char dynsm[];
    constexpr int NI = BN / 16;
    constexpr int NP = BN / 32;
    constexpr uint32_t BSTRIDE = BN * 128;
    const uint32_t asb = smem_u32(dynsm);
    const uint32_t bsb = asb + 3 * 16384u;
    const int tid = threadIdx.x, lane = tid & 31, wid = tid >> 5;
    const int z = blockIdx.z, m0 = blockIdx.y * 128, n0 = blockIdx.x * BN;
    const int wm = wid & 3, wn = wid >> 2;
    const int aoff = z * aoffz;
    const bf* Bh = Bhi + (size_t)z * bz;
    const bf* Bl = Blo ? (Blo + (size_t)z * bz) : Bh;
    const int kc = K >> 6, nch = npass * kc;

    const int lr = tid >> 3;
    const int lch = tid & 7;
    const uint32_t lsw = (uint32_t)((lch ^ (lr & 7)) * 16);

    auto issue = [&](int c) {
        int pass = c / kc, k0 = (c - pass * kc) << 6;
        const bf* Ap = (pass == 2) ? Alo : Ahi;
        const bf* Bp = (pass == 1) ? Bl : Bh;
        int buf = c % 3;
        uint32_t sa = asb + buf * 16384u, sb = bsb + buf * BSTRIDE;
#pragma unroll
        for (int i = 0; i < 4; i++) {
            int rr = lr + 32 * i;
            cp16(sa + rr * 128 + lsw, Ap + (size_t)(m0 + rr) * lda + aoff + k0 + lch * 8);
        }
#pragma unroll
        for (int i = 0; i < NP; i++) {
            int rr = lr + 32 * i;
            cp16(sb + rr * 128 + lsw, Bp + (size_t)(n0 + rr) * ldb + k0 + lch * 8);
        }
        cp_commit();
    };

    float acc[2][NI][4];
#pragma unroll
    for (int i = 0; i < 2; i++)
#pragma unroll
        for (int j = 0; j < NI; j++)
#pragma unroll
            for (int k = 0; k < 4; k++) acc[i][j][k] = 0.f;

    issue(0);
    if (nch > 1) issue(1); else cp_commit();

    for (int i = 0; i < nch; i++) {
        cp_wait1();
        __syncthreads();
        if (i + 2 < nch) issue(i + 2); else cp_commit();
        uint32_t ab = asb + (i % 3) * 16384u;
        uint32_t bb = bsb + (i % 3) * BSTRIDE;
#pragma unroll
        for (int s = 0; s < 4; s++) {
            uint32_t bq[NP][4];
#pragma unroll
            for (int np = 0; np < NP; np++) {
                int g = lane >> 3;
                int brow = wn * (BN / 2) + np * 16 + (g >> 1) * 8 + (lane & 7);
                int bch = s * 2 + (g & 1);
                ldmB4(bq[np], bb + brow * 128 + ((bch ^ (brow & 7)) * 16));
            }
#pragma unroll
            for (int mi = 0; mi < 2; mi++) {
                int arow = wm * 32 + mi * 16 + (lane & 15);
                int ach = s * 2 + (lane >> 4);
                uint32_t afr[4];
                ldmA(afr, ab + arow * 128 + ((ach ^ (arow & 7)) * 16));
#pragma unroll
                for (int ni = 0; ni < NI; ni++)
                    mma16816(acc[mi][ni], afr, &bq[ni >> 1][(ni & 1) * 2]);
            }
        }
    }

    const int r0 = lane >> 2, cp = (lane & 3) * 2;
#pragma unroll
    for (int mi = 0; mi < 2; mi++) {
#pragma unroll
        for (int half = 0; half < 2; half++) {
            int row = m0 + wm * 32 + mi * 16 + r0 + half * 8;
#pragma unroll
            for (int ni = 0; ni < NI; ni++) {
                int col = n0 + wn * (BN / 2) + ni * 8 + cp;
                float v0 = acc[mi][ni][half * 2 + 0];
                float v1 = acc[mi][ni][half * 2 + 1];
                bool qside = (mode == 2) || (mode == 3 && col >= nsplit);
                if (mode == 1) {
                    size_t off = (size_t)row * ldc + z * coffz + col;
                    size_t eo = (size_t)row * lde + z * eoffz + col;
                    float2 ev = *(const float2*)(E + eo);
                    float2 o;
                    o.x = fmaxf(v0 + ev.x, 0.f);
                    o.y = fmaxf(v1 + ev.y, 0.f);
                    *(float2*)(C + off) = o;
                } else if (qside) {
                    size_t off = (size_t)row * ldc + z * coffz + (col - nsplit);
                    __nv_bfloat162 hh;
                    hh.x = __float2bfloat16(v0);
                    hh.y = __float2bfloat16(v1);
                    *(__nv_bfloat162*)(Chi + off) = hh;
                } else {
                    size_t off = (size_t)row * ldc + z * coffz + col;
                    float2 o; o.x = v0; o.y = v1;
                    *(float2*)(C + off) = o;
                }
            }
        }
    }
}

// ---------------- fused attention layer 1 (cp.async gather, u in bf16) ----------------
__global__ __launch_bounds__(256) void attn1_kernel(const float* __restrict__ emb) {
    __shared__ __align__(16) float sh2[FAN_2][EMB];
    int n = blockIdx.x, tid = threadIdx.x;
    uint32_t sb = smem_u32(sh2);
    // gather 10 x 1KB rows as 640 16B cp.async chunks
    for (int c = tid; c < FAN_2 * 64; c += 256) {
        int f = c >> 6, c16 = c & 63;
        cp16(sb + c * 16, emb + (size_t)g_nbr2[n * FAN_2 + f] * EMB + c16 * 4);
    }
    cp_commit();
    int w = tid >> 5, l = tid & 31;
    const bf* up = g_u1 + (size_t)n * (HEADS * EMB) + w * EMB;
    float u[8];
#pragma unroll
    for (int j = 0; j < 8; j++) u[j] = __bfloat162float(up[l + j * 32]);   // overlaps gather
    cp_wait0();
    __syncthreads();

    float at[FAN_2], mx = -1e30f;
#pragma unroll
    for (int f = 0; f < FAN_2; f++) {
        float p = 0.f;
#pragma unroll
        for (int j = 0; j < 8; j++) p += sh2[f][l + j * 32] * u[j];
#pragma unroll
        for (int o = 16; o; o >>= 1) p += __shfl_xor_sync(0xffffffffu, p, o);
        p *= 0.125f;
        at[f] = p; mx = fmaxf(mx, p);
    }
    float s = 0.f;
#pragma unroll
    for (int f = 0; f < FAN_2; f++) { at[f] = expf(at[f] - mx); s += at[f]; }
    float inv = 1.f / s;
    size_t mo = (size_t)n * (HEADS * EMB) + w * EMB;
#pragma unroll
    for (int j = 0; j < 8; j++) {
        int e = l + j * 32;
        float m = 0.f;
#pragma unroll
        for (int f = 0; f < FAN_2; f++) m += at[f] * sh2[f][e];
        m *= inv;
        bf h = __float2bfloat16(m);
        g_m1hi[mo + e] = h;
        g_m1lo[mo + e] = __float2bfloat16(m - __bfloat162float(h));
    }
}

// ---------------- fused attention layer 2 (cp.async load, u in bf16) ----------------
__global__ __launch_bounds__(256) void attn2_kernel() {
    __shared__ __align__(16) float sh1[FAN_1][HID];
    int b = blockIdx.x, tid = threadIdx.x;
    uint32_t sb = smem_u32(sh1);
    const char* hp = (const char*)(g_h1 + (size_t)b * FAN_1 * HID);
    for (int c = tid; c < FAN_1 * HID / 4; c += 256)
        cp16(sb + c * 16, hp + (size_t)c * 16);
    cp_commit();
    int w = tid >> 5, l = tid & 31;
    const bf* up = g_u2 + (size_t)b * (HEADS * HID) + w * HID;
    float u[16];
#pragma unroll
    for (int j = 0; j < 16; j++) u[j] = __bfloat162float(up[l + j * 32]);
    cp_wait0();
    __syncthreads();

    float at[FAN_1], mx = -1e30f;
#pragma unroll
    for (int f = 0; f < FAN_1; f++) {
        float p = 0.f;
#pragma unroll
        for (int j = 0; j < 16; j++) p += sh1[f][l + j * 32] * u[j];
#pragma unroll
        for (int o = 16; o; o >>= 1) p += __shfl_xor_sync(0xffffffffu, p, o);
        p *= 0.125f;
        at[f] = p; mx = fmaxf(mx, p);
    }
    float s = 0.f;
#pragma unroll
    for (int f = 0; f < FAN_1; f++) { at[f] = expf(at[f] - mx); s += at[f]; }
    float inv = 1.f / s;
    size_t mo = (size_t)b * (HEADS * HID) + w * HID;
#pragma unroll
    for (int j = 0; j < 16; j++) {
        int e = l + j * 32;
        float m = 0.f;
#pragma unroll
        for (int f = 0; f < FAN_1; f++) m += at[f] * sh1[f][e];
        m *= inv;
        bf h = __float2bfloat16(m);
        g_m2hi[mo + e] = h;
        g_m2lo[mo + e] = __float2bfloat16(m - __bfloat162float(h));
    }
}

// ---------------- host ----------------
#define GET(n) void* p_##n; cudaGetSymbolAddress(&p_##n, g_##n)
#define DSM128 (3 * 16384 + 3 * 128 * 128)   /* 98304 */
#define DSM64  (3 * 16384 + 3 * 64 * 128)    /* 73728 */

extern "C" void kernel_launch(void* const* d_in, const int* in_sizes, int n_in,
                              void* d_out, int out_size) {
    const void* seeds = d_in[0];
    const void* nbr1  = d_in[1];
    const void* nbr2  = d_in[2];
    const float* emb = (const float*)d_in[3];
    const float* Wq1 = (const float*)d_in[4];
    const float* Wk1 = (const float*)d_in[5];
    const float* Wv1 = (const float*)d_in[6];
    const float* Ws1 = (const float*)d_in[7];
    const float* Wq2 = (const float*)d_in[8];
    const float* Wk2 = (const float*)d_in[9];
    const float* Wv2 = (const float*)d_in[10];
    const float* Ws2 = (const float*)d_in[11];
    float* out = (float*)d_out;

    GET(Bs1hi); GET(Bs1lo); GET(Bq1hi); GET(Bq1lo);
    GET(B2chi); GET(B2clo);
    GET(Wv1hi); GET(Wv1lo); GET(Wv2hi); GET(Wv2lo);
    GET(Wk1thi); GET(Wk1tlo); GET(Wk2thi); GET(Wk2tlo);
    GET(A1hi); GET(A1lo); GET(A2hi); GET(A2lo);
    GET(s1); GET(q1hi); GET(u1); GET(m1hi); GET(m1lo); GET(h1);
    GET(s2); GET(q2hi); GET(u2); GET(m2hi); GET(m2lo);

    cudaFuncSetAttribute(mma_gemm<128>, cudaFuncAttributeMaxDynamicSharedMemorySize, DSM128);
    cudaFuncSetAttribute(mma_gemm<64>,  cudaFuncAttributeMaxDynamicSharedMemorySize, DSM64);

    // 0: mega prep (weights, nbr2 convert, both gathers — raw idx decoded inline)
    prep_mega<<<PREP_BLOCKS, 256>>>(Ws1, Wq1, Ws2, Wq2, Wv1, Wv2, Wk1, Wk2,
                                    seeds, nbr1, nbr2, emb);
    // 1: q1 = A1 @ Wq1^T (1-pass, bf16)
    mma_gemm<128><<<dim3(4, 120, 1), 256, DSM128>>>(
        nullptr, (bf*)p_q1hi, HID, 0, nullptr, 0, 0, 2, 0, 1,
        (bf*)p_A1hi, (bf*)p_A1hi, EMB, 0, (bf*)p_Bq1hi, nullptr, EMB, 0, EMB);
    // 2: u1 = q1_h @ Wk1t_h^T (1-pass, bf16), K=64
    mma_gemm<128><<<dim3(2, 120, 8), 256, DSM128>>>(
        nullptr, (bf*)p_u1, HEADS * EMB, EMB, nullptr, 0, 0, 2, 0, 1,
        (bf*)p_q1hi, (bf*)p_q1hi, HID, 64, (bf*)p_Wk1thi, nullptr, 64, EMB * 64, 64);
    // 3: attention layer 1  <-- PROFILED
    attn1_kernel<<<N1, 256>>>(emb);
    // 4: s1 = A1 @ Ws1^T (3-pass fp32)
    mma_gemm<128><<<dim3(4, 120, 1), 256, DSM128>>>(
        (float*)p_s1, nullptr, HID, 0, nullptr, 0, 0, 0, 0, 3,
        (bf*)p_A1hi, (bf*)p_A1lo, EMB, 0, (bf*)p_Bs1hi, (bf*)p_Bs1lo, EMB, 0, EMB);
    // 5: h1 = relu(s1 + m1_h @ Wv1_h^T) (3-pass), N=64 per head
    mma_gemm<64><<<dim3(1, 120, 8), 256, DSM64>>>(
        (float*)p_h1, nullptr, HID, 64, (const float*)p_s1, HID, 64, 1, 0, 3,
        (bf*)p_m1hi, (bf*)p_m1lo, HEADS * EMB, EMB, (bf*)p_Wv1hi, (bf*)p_Wv1lo, EMB, 64 * EMB, EMB);
    // 6: [s2 | q2] = A2 @ [Ws2;Wq2]^T (3-pass, split epilogue)
    mma_gemm<128><<<dim3(8, 8, 1), 256, DSM128>>>(
        (float*)p_s2, (bf*)p_q2hi, HID, 0, nullptr, 0, 0, 3, HID, 3,
        (bf*)p_A2hi, (bf*)p_A2lo, EMB, 0, (bf*)p_B2chi, (bf*)p_B2clo, EMB, 0, EMB);
    // 7: u2 = q2_h @ Wk2t_h^T (1-pass, bf16), K=64
    mma_gemm<128><<<dim3(4, 8, 8), 256, DSM128>>>(
        nullptr, (bf*)p_u2, HEADS * HID, HID, nullptr, 0, 0, 2, 0, 1,
        (bf*)p_q2hi, (bf*)p_q2hi, HID, 64, (bf*)p_Wk2thi, nullptr, 64, HID * 64, 64);
    // 8: attention layer 2
    attn2_kernel<<<NB_B, 256>>>();
    // 9: out = relu(s2 + m2_h @ Wv2_h^T) (3-pass), K=512, N=64 per head
    mma_gemm<64><<<dim3(1, 8, 8), 256, DSM64>>>(
        out, nullptr, HID, 64, (const float*)p_s2, HID, 64, 1, 0, 3,
        (bf*)p_m2hi, (bf*)p_m2lo, HEADS * HID, HID, (bf*)p_Wv2hi, (bf*)p_Wv2lo, HID, 64 * HID, HID);
}